// round 1
// baseline (speedup 1.0000x reference)
#include <cuda_runtime.h>
#include <math.h>

// ---------------------------------------------------------------------------
// ViT block: patch-embed GEMM -> LN(S,E) -> QKV -> 4-head attention ->
// Wo + residual -> LN(S,E).  B=64, S=196, E=768, H=4, HD=192.
// Round 0: fp32 baseline. All GEMMs via one tiled SGEMM (128x64x16, 8x4/thr).
// ---------------------------------------------------------------------------

#define BB   64
#define SS   196
#define EE   768
#define HH   4
#define HDIM 192
#define PP   16
#define GG   14
#define MM   (BB * SS)        // 12544
#define SE   (SS * EE)        // 150528

#define BM 128
#define BN 64
#define BK 16

// Scratch (device globals: allocation-free per harness rules)
__device__ float g_patches[MM * EE];
__device__ float g_emb[MM * EE];
__device__ float g_h[MM * EE];
__device__ float g_q[MM * EE];
__device__ float g_k[MM * EE];
__device__ float g_v[MM * EE];
__device__ float g_att[MM * EE];
__device__ float g_res[MM * EE];
__device__ float g_scores[BB * HH * SS * SS];   // 9,834,496 floats
__device__ float g_stats1[BB * 2];
__device__ float g_stats2[BB * 2];

// ---------------------------------------------------------------------------
// im2col: x[B,3,224,224] -> patches[B*S, 768] with inner = c*256 + py*16 + px
// ---------------------------------------------------------------------------
__global__ void im2col_kernel(const float* __restrict__ x, float* __restrict__ out) {
    int idx = blockIdx.x * blockDim.x + threadIdx.x;
    if (idx >= MM * EE) return;
    int e = idx % EE;
    int s = (idx / EE) % SS;
    int b = idx / (EE * SS);
    int c = e >> 8;           // e / 256
    int r = e & 255;
    int py = r >> 4;
    int px = r & 15;
    int gy = s / GG;
    int gx = s % GG;
    out[idx] = x[(((long)(b * 3 + c) * 224) + gy * PP + py) * 224 + gx * PP + px];
}

// ---------------------------------------------------------------------------
// Generic batched GEMM:  C = scale * A * op(B) + bias + resid
//   A: [M,K] row-major (lda).  TRANS_B: B is [N,K] (lda=ldb, dot over K, "NT")
//   else B is [K,N] ("NN").  Batch offset: z -> (z/Hdiv, z%Hdiv) * strides.
// ---------------------------------------------------------------------------
template <bool TRANS_B>
__global__ void __launch_bounds__(256)
gemm_kernel(const float* __restrict__ A, const float* __restrict__ Bm,
            const float* __restrict__ bias, const float* __restrict__ resid,
            float* __restrict__ C,
            int Md, int Nd, int Kd, int lda, int ldb, int ldc,
            int Hdiv,
            long sA1, long sA2, long sB1, long sB2, long sC1, long sC2,
            float scale)
{
    __shared__ float As[BK][BM];
    __shared__ float Bs[BK][BN];

    int z = blockIdx.z;
    int z1 = z / Hdiv, z2 = z % Hdiv;
    A  += z1 * sA1 + z2 * sA2;
    Bm += z1 * sB1 + z2 * sB2;
    long coff = z1 * sC1 + z2 * sC2;
    C += coff;
    if (resid) resid += coff;

    int tid = threadIdx.x;
    int tx = tid & 15;        // 0..15 -> 4 cols each
    int ty = tid >> 4;        // 0..15 -> 8 rows each
    int m0 = blockIdx.x * BM;
    int n0 = blockIdx.y * BN;

    float acc[8][4];
#pragma unroll
    for (int i = 0; i < 8; i++)
#pragma unroll
        for (int j = 0; j < 4; j++) acc[i][j] = 0.0f;

    for (int k0 = 0; k0 < Kd; k0 += BK) {
        // ---- load A tile (transposed into As[k][m]) : 512 float4, 2/thread
#pragma unroll
        for (int i = 0; i < 2; i++) {
            int f4 = tid + i * 256;
            int m  = f4 >> 2;
            int kf = (f4 & 3) * 4;
            int gm = m0 + m, gk = k0 + kf;
            float4 v = make_float4(0.f, 0.f, 0.f, 0.f);
            if (gm < Md) {
                if (gk + 3 < Kd) {
                    v = *(const float4*)(A + (long)gm * lda + gk);
                } else {
                    float t0 = (gk + 0 < Kd) ? A[(long)gm * lda + gk + 0] : 0.f;
                    float t1 = (gk + 1 < Kd) ? A[(long)gm * lda + gk + 1] : 0.f;
                    float t2 = (gk + 2 < Kd) ? A[(long)gm * lda + gk + 2] : 0.f;
                    float t3 = (gk + 3 < Kd) ? A[(long)gm * lda + gk + 3] : 0.f;
                    v = make_float4(t0, t1, t2, t3);
                }
            }
            As[kf + 0][m] = v.x;
            As[kf + 1][m] = v.y;
            As[kf + 2][m] = v.z;
            As[kf + 3][m] = v.w;
        }
        // ---- load B tile into Bs[k][n]
        if (TRANS_B) {
            int f4 = tid;              // 256 float4 = 64 rows * 4
            int n  = f4 >> 2;
            int kf = (f4 & 3) * 4;
            int gn = n0 + n, gk = k0 + kf;
            float4 v = make_float4(0.f, 0.f, 0.f, 0.f);
            if (gn < Nd) {
                if (gk + 3 < Kd) {
                    v = *(const float4*)(Bm + (long)gn * ldb + gk);
                } else {
                    float t0 = (gk + 0 < Kd) ? Bm[(long)gn * ldb + gk + 0] : 0.f;
                    float t1 = (gk + 1 < Kd) ? Bm[(long)gn * ldb + gk + 1] : 0.f;
                    float t2 = (gk + 2 < Kd) ? Bm[(long)gn * ldb + gk + 2] : 0.f;
                    float t3 = (gk + 3 < Kd) ? Bm[(long)gn * ldb + gk + 3] : 0.f;
                    v = make_float4(t0, t1, t2, t3);
                }
            }
            Bs[kf + 0][n] = v.x;
            Bs[kf + 1][n] = v.y;
            Bs[kf + 2][n] = v.z;
            Bs[kf + 3][n] = v.w;
        } else {
            int k  = tid >> 4;         // 0..15
            int nf = (tid & 15) * 4;   // 0..60
            int gk = k0 + k, gn = n0 + nf;
            float4 v = make_float4(0.f, 0.f, 0.f, 0.f);
            if (gk < Kd) {
                if (gn + 3 < Nd) {
                    v = *(const float4*)(Bm + (long)gk * ldb + gn);
                } else {
                    float t0 = (gn + 0 < Nd) ? Bm[(long)gk * ldb + gn + 0] : 0.f;
                    float t1 = (gn + 1 < Nd) ? Bm[(long)gk * ldb + gn + 1] : 0.f;
                    float t2 = (gn + 2 < Nd) ? Bm[(long)gk * ldb + gn + 2] : 0.f;
                    float t3 = (gn + 3 < Nd) ? Bm[(long)gk * ldb + gn + 3] : 0.f;
                    v = make_float4(t0, t1, t2, t3);
                }
            }
            *(float4*)&Bs[k][nf] = v;
        }
        __syncthreads();

#pragma unroll
        for (int k = 0; k < BK; k++) {
            float a[8], b[4];
#pragma unroll
            for (int i = 0; i < 8; i++) a[i] = As[k][ty * 8 + i];
#pragma unroll
            for (int j = 0; j < 4; j++) b[j] = Bs[k][tx * 4 + j];
#pragma unroll
            for (int i = 0; i < 8; i++)
#pragma unroll
                for (int j = 0; j < 4; j++) acc[i][j] += a[i] * b[j];
        }
        __syncthreads();
    }

    // epilogue
#pragma unroll
    for (int i = 0; i < 8; i++) {
        int gm = m0 + ty * 8 + i;
        if (gm >= Md) continue;
#pragma unroll
        for (int j = 0; j < 4; j++) {
            int gn = n0 + tx * 4 + j;
            if (gn >= Nd) continue;
            float v = acc[i][j] * scale;
            if (bias)  v += bias[gn];
            if (resid) v += resid[(long)gm * ldc + gn];
            C[(long)gm * ldc + gn] = v;
        }
    }
}

// ---------------------------------------------------------------------------
// LayerNorm over (S,E) per batch image: reduce then apply
// ---------------------------------------------------------------------------
__global__ void ln_reduce_kernel(const float* __restrict__ in, float* __restrict__ stats) {
    int b = blockIdx.x;
    const float4* p = (const float4*)(in + (long)b * SE);
    float s = 0.f, s2 = 0.f;
    for (int i = threadIdx.x; i < SE / 4; i += blockDim.x) {
        float4 v = p[i];
        s  += v.x + v.y + v.z + v.w;
        s2 += v.x * v.x + v.y * v.y + v.z * v.z + v.w * v.w;
    }
    __shared__ float sh[256], sh2[256];
    sh[threadIdx.x] = s; sh2[threadIdx.x] = s2;
    __syncthreads();
    for (int st = 128; st > 0; st >>= 1) {
        if (threadIdx.x < st) {
            sh[threadIdx.x]  += sh[threadIdx.x + st];
            sh2[threadIdx.x] += sh2[threadIdx.x + st];
        }
        __syncthreads();
    }
    if (threadIdx.x == 0) {
        float mu  = sh[0] / (float)SE;
        float var = sh2[0] / (float)SE - mu * mu;
        stats[b * 2 + 0] = mu;
        stats[b * 2 + 1] = rsqrtf(var + 1e-5f);
    }
}

__global__ void ln_apply_kernel(const float* __restrict__ in, const float* __restrict__ stats,
                                const float* __restrict__ w, const float* __restrict__ bw,
                                float* __restrict__ out) {
    int i4 = blockIdx.x * blockDim.x + threadIdx.x;   // float4 index
    if (i4 >= (MM * EE) / 4) return;
    int b   = i4 / (SE / 4);
    int se4 = i4 - b * (SE / 4);
    float mu = stats[b * 2 + 0], rs = stats[b * 2 + 1];
    float4 v  = ((const float4*)in)[i4];
    float4 wv = ((const float4*)w)[se4];
    float4 bv = ((const float4*)bw)[se4];
    float4 o;
    o.x = (v.x - mu) * rs * wv.x + bv.x;
    o.y = (v.y - mu) * rs * wv.y + bv.y;
    o.z = (v.z - mu) * rs * wv.z + bv.z;
    o.w = (v.w - mu) * rs * wv.w + bv.w;
    ((float4*)out)[i4] = o;
}

// ---------------------------------------------------------------------------
// Softmax over last dim (196), one warp per row
// ---------------------------------------------------------------------------
__global__ void softmax_kernel(float* __restrict__ sc, int rows, int cols) {
    int warp = threadIdx.x >> 5, lane = threadIdx.x & 31;
    int row = blockIdx.x * 4 + warp;
    if (row >= rows) return;
    float* p = sc + (long)row * cols;
    float v[7];
    float mx = -1e30f;
#pragma unroll
    for (int i = 0; i < 7; i++) {
        int idx = lane + i * 32;
        v[i] = (idx < cols) ? p[idx] : -1e30f;
        mx = fmaxf(mx, v[i]);
    }
#pragma unroll
    for (int o = 16; o > 0; o >>= 1) mx = fmaxf(mx, __shfl_xor_sync(0xFFFFFFFFu, mx, o));
    float sum = 0.f;
#pragma unroll
    for (int i = 0; i < 7; i++) { v[i] = expf(v[i] - mx); sum += v[i]; }
#pragma unroll
    for (int o = 16; o > 0; o >>= 1) sum += __shfl_xor_sync(0xFFFFFFFFu, sum, o);
    float inv = 1.0f / sum;
#pragma unroll
    for (int i = 0; i < 7; i++) {
        int idx = lane + i * 32;
        if (idx < cols) p[idx] = v[i] * inv;
    }
}

// ---------------------------------------------------------------------------
extern "C" void kernel_launch(void* const* d_in, const int* in_sizes, int n_in,
                              void* d_out, int out_size) {
    const float* x      = (const float*)d_in[0];
    const float* conv_w = (const float*)d_in[1];
    const float* conv_b = (const float*)d_in[2];
    const float* wq = (const float*)d_in[3];
    const float* bq = (const float*)d_in[4];
    const float* wk = (const float*)d_in[5];
    const float* bk = (const float*)d_in[6];
    const float* wv = (const float*)d_in[7];
    const float* bv = (const float*)d_in[8];
    const float* wo = (const float*)d_in[9];
    const float* bo = (const float*)d_in[10];
    const float* ln1w = (const float*)d_in[11];
    const float* ln1b = (const float*)d_in[12];
    const float* ln2w = (const float*)d_in[13];
    const float* ln2b = (const float*)d_in[14];
    float* out = (float*)d_out;

    float *patches, *emb, *h, *q, *k, *v, *att, *res, *scores, *st1, *st2;
    cudaGetSymbolAddress((void**)&patches, g_patches);
    cudaGetSymbolAddress((void**)&emb,     g_emb);
    cudaGetSymbolAddress((void**)&h,       g_h);
    cudaGetSymbolAddress((void**)&q,       g_q);
    cudaGetSymbolAddress((void**)&k,       g_k);
    cudaGetSymbolAddress((void**)&v,       g_v);
    cudaGetSymbolAddress((void**)&att,     g_att);
    cudaGetSymbolAddress((void**)&res,     g_res);
    cudaGetSymbolAddress((void**)&scores,  g_scores);
    cudaGetSymbolAddress((void**)&st1,     g_stats1);
    cudaGetSymbolAddress((void**)&st2,     g_stats2);

    const int total  = MM * EE;
    const dim3 gemm_grid(MM / BM, EE / BN, 1);           // 98 x 12
    const float scale = 1.0f / sqrtf((float)HDIM);

    // 1. im2col
    im2col_kernel<<<(total + 255) / 256, 256>>>(x, patches);

    // 2. patch embed GEMM: emb = patches @ conv_w^T + conv_b
    gemm_kernel<true><<<gemm_grid, 256>>>(patches, conv_w, conv_b, nullptr, emb,
        MM, EE, EE, EE, EE, EE, 1, 0, 0, 0, 0, 0, 0, 1.0f);

    // 3. LN1
    ln_reduce_kernel<<<BB, 256>>>(emb, st1);
    ln_apply_kernel<<<(total / 4 + 255) / 256, 256>>>(emb, st1, ln1w, ln1b, h);

    // 4. QKV projections
    gemm_kernel<true><<<gemm_grid, 256>>>(h, wq, bq, nullptr, q,
        MM, EE, EE, EE, EE, EE, 1, 0, 0, 0, 0, 0, 0, 1.0f);
    gemm_kernel<true><<<gemm_grid, 256>>>(h, wk, bk, nullptr, k,
        MM, EE, EE, EE, EE, EE, 1, 0, 0, 0, 0, 0, 0, 1.0f);
    gemm_kernel<true><<<gemm_grid, 256>>>(h, wv, bv, nullptr, v,
        MM, EE, EE, EE, EE, EE, 1, 0, 0, 0, 0, 0, 0, 1.0f);

    // 5. scores = scale * Q @ K^T   (batched over B*H = 256)
    gemm_kernel<true><<<dim3(2, 4, BB * HH), 256>>>(q, k, nullptr, nullptr, scores,
        SS, SS, HDIM, EE, EE, SS,
        HH, (long)SE, (long)HDIM, (long)SE, (long)HDIM,
        (long)HH * SS * SS, (long)SS * SS, scale);

    // 6. softmax
    softmax_kernel<<<(BB * HH * SS) / 4, 128>>>(scores, BB * HH * SS, SS);

    // 7. O = attn @ V  (batched, NN)
    gemm_kernel<false><<<dim3(2, 3, BB * HH), 256>>>(scores, v, nullptr, nullptr, att,
        SS, HDIM, SS, SS, EE, EE,
        HH, (long)HH * SS * SS, (long)SS * SS, (long)SE, (long)HDIM,
        (long)SE, (long)HDIM, 1.0f);

    // 8. out proj + residual: res = emb + att @ wo^T + bo
    gemm_kernel<true><<<gemm_grid, 256>>>(att, wo, bo, emb, res,
        MM, EE, EE, EE, EE, EE, 1, 0, 0, 0, 0, 0, 0, 1.0f);

    // 9. LN2 -> out
    ln_reduce_kernel<<<BB, 256>>>(res, st2);
    ln_apply_kernel<<<(total / 4 + 255) / 256, 256>>>(res, st2, ln2w, ln2b, out);
}

// round 3
// speedup vs baseline: 3.5436x; 3.5436x over previous
#include <cuda_runtime.h>
#include <cuda_bf16.h>
#include <cstdint>
#include <math.h>

// ---------------------------------------------------------------------------
// ViT block on GB300. R3: big GEMMs (patch-embed, Q, K, V, Wo) via mma.sync
// bf16 HMMA (generic-target; tcgen05 unavailable: harness emits compute_103
// PTX). bf16x3 split precision: K' = 3*768 = 2304.
// Attention stays fp32 SGEMM this round.
// ---------------------------------------------------------------------------

#define BB   64
#define SS   196
#define EE   768
#define HH   4
#define HDIM 192
#define PP   16
#define GG   14
#define MM   (BB * SS)        // 12544
#define SE   (SS * EE)        // 150528
#define KP   (3 * EE)         // 2304
#define NKC  (KP / 32)        // 72 k-chunks of 32

// ---------------- scratch ---------------------------------------------------
__device__ float g_emb[MM * EE];
__device__ float g_q[MM * EE];
__device__ float g_k[MM * EE];
__device__ float g_v[MM * EE];
__device__ float g_att[MM * EE];
__device__ float g_res[MM * EE];
__device__ float g_scores[BB * HH * SS * SS];
__device__ float g_stats1[BB * 2];
__device__ float g_stats2[BB * 2];
__device__ __nv_bfloat16 g_a16[(size_t)MM * KP];
__device__ __nv_bfloat16 g_w16[5][(size_t)EE * KP];

// ---------------- helpers ---------------------------------------------------
__device__ __forceinline__ uint32_t smem_u32(const void* p) {
    uint32_t a;
    asm("{ .reg .u64 t; cvta.to.shared.u64 t, %1; cvt.u32.u64 %0, t; }" : "=r"(a) : "l"(p));
    return a;
}
__device__ __forceinline__ void cp16(uint32_t saddr, const void* g) {
    asm volatile("cp.async.cg.shared.global [%0], [%1], 16;"
                 :: "r"(saddr), "l"(__cvta_generic_to_global(g)));
}
#define CP_COMMIT() asm volatile("cp.async.commit_group;" ::: "memory")
#define CP_WAIT1()  asm volatile("cp.async.wait_group 1;" ::: "memory")
#define CP_WAIT0()  asm volatile("cp.async.wait_group 0;" ::: "memory")

__device__ __forceinline__ void ldm_x4(uint32_t* r, uint32_t addr) {
    asm volatile("ldmatrix.sync.aligned.m8n8.x4.shared.b16 {%0,%1,%2,%3}, [%4];"
                 : "=r"(r[0]), "=r"(r[1]), "=r"(r[2]), "=r"(r[3]) : "r"(addr));
}
__device__ __forceinline__ void mma16816(float* c, const uint32_t* a, uint32_t b0, uint32_t b1) {
    asm volatile("mma.sync.aligned.m16n8k16.row.col.f32.bf16.bf16.f32 "
                 "{%0,%1,%2,%3}, {%4,%5,%6,%7}, {%8,%9}, {%0,%1,%2,%3};"
                 : "+f"(c[0]), "+f"(c[1]), "+f"(c[2]), "+f"(c[3])
                 : "r"(a[0]), "r"(a[1]), "r"(a[2]), "r"(a[3]), "r"(b0), "r"(b1));
}

// ---------------------------------------------------------------------------
// HMMA GEMM: C[M,768] = A[M,2304]bf16 . B[768,2304]bf16^T (+bias)(+resid)
// Tile 128x128x32, 8 warps (2x4), double-buffered cp.async.
// Smem row = 64B (32 bf16); swizzle: chunk ^= (row>>1)&3  (16B chunks).
// ---------------------------------------------------------------------------
__global__ void __launch_bounds__(256, 2)
hmma_gemm_kernel(const __nv_bfloat16* __restrict__ A, const __nv_bfloat16* __restrict__ Bw,
                 const float* __restrict__ bias, const float* __restrict__ resid,
                 float* __restrict__ C)
{
    __shared__ __align__(1024) char smem[32768];   // A:2x8KB, B:2x8KB
    const uint32_t sb = smem_u32(smem);
    const int tid = threadIdx.x;
    const int lane = tid & 31, wid = tid >> 5;
    const int wm = wid & 1, wn = wid >> 1;          // 2 x 4 warp grid
    const int m0 = blockIdx.x * 128, n0 = blockIdx.y * 128;

    const __nv_bfloat16* Abase = A + (long)m0 * KP;
    const __nv_bfloat16* Bbase = Bw + (long)n0 * KP;

    // stage loader: 512 16B-chunks each for A and B; 2+2 per thread
#define LOAD_STAGE(buf, kc) do {                                              \
        int _ko = (kc) * 32;                                                  \
        _Pragma("unroll")                                                     \
        for (int _i = 0; _i < 2; _i++) {                                      \
            int _lin = tid + _i * 256;                                        \
            int _row = _lin >> 2, _ch = _lin & 3;                             \
            uint32_t _sw = (uint32_t)(_row * 64 + ((_ch ^ ((_row >> 1) & 3)) << 4)); \
            cp16(sb + (buf) * 8192 + _sw,         Abase + (long)_row * KP + _ko + _ch * 8); \
            cp16(sb + 16384 + (buf) * 8192 + _sw, Bbase + (long)_row * KP + _ko + _ch * 8); \
        }                                                                     \
    } while (0)

    float acc[4][4][4] = {};

    // lane-invariant ldmatrix address pieces
    const int g = lane >> 3, r8 = lane & 7;
    const int rA = (g & 1) * 8 + r8, selA = (rA >> 1) & 3, chA = g >> 1;
    const int rB = (g >> 1) * 8 + r8, selB = (rB >> 1) & 3, chB = g & 1;

    LOAD_STAGE(0, 0); CP_COMMIT();
    LOAD_STAGE(1, 1); CP_COMMIT();

    for (int kc = 0; kc < NKC; kc++) {
        const int buf = kc & 1;
        if (kc < NKC - 2) CP_WAIT1(); else CP_WAIT0();
        __syncthreads();
        const uint32_t sA = sb + buf * 8192;
        const uint32_t sB = sb + 16384 + buf * 8192;
#pragma unroll
        for (int ks = 0; ks < 2; ks++) {
            const int k2 = ks * 2;
            uint32_t a[4][4], b[2][4];
#pragma unroll
            for (int mt = 0; mt < 4; mt++) {
                int row = wm * 64 + mt * 16 + rA;
                ldm_x4(a[mt], sA + row * 64 + (((k2 + chA) ^ selA) << 4));
            }
#pragma unroll
            for (int p = 0; p < 2; p++) {
                int row = wn * 32 + p * 16 + rB;
                ldm_x4(b[p], sB + row * 64 + (((k2 + chB) ^ selB) << 4));
            }
#pragma unroll
            for (int mt = 0; mt < 4; mt++)
#pragma unroll
                for (int nt = 0; nt < 4; nt++)
                    mma16816(acc[mt][nt], a[mt], b[nt >> 1][(nt & 1) * 2], b[nt >> 1][(nt & 1) * 2 + 1]);
        }
        __syncthreads();
        if (kc + 2 < NKC) { LOAD_STAGE(buf, kc + 2); CP_COMMIT(); }
    }
#undef LOAD_STAGE

    // epilogue
#pragma unroll
    for (int mt = 0; mt < 4; mt++) {
        const int gm = m0 + wm * 64 + mt * 16 + (lane >> 2);
#pragma unroll
        for (int nt = 0; nt < 4; nt++) {
            const int gn = n0 + wn * 32 + nt * 8 + (lane & 3) * 2;
            const float* c = acc[mt][nt];
            float b0 = bias[gn], b1 = bias[gn + 1];
            float2 v0 = make_float2(c[0] + b0, c[1] + b1);
            float2 v1 = make_float2(c[2] + b0, c[3] + b1);
            if (resid) {
                float2 r0 = *(const float2*)(resid + (long)gm * EE + gn);
                float2 r1 = *(const float2*)(resid + (long)(gm + 8) * EE + gn);
                v0.x += r0.x; v0.y += r0.y; v1.x += r1.x; v1.y += r1.y;
            }
            *(float2*)(C + (long)gm * EE + gn) = v0;
            *(float2*)(C + (long)(gm + 8) * EE + gn) = v1;
        }
    }
}

// ---------------------------------------------------------------------------
// splits: fp32 -> bf16 hi/lo triple along K
// activations: [hi | lo | hi], weights: [hi | hi | lo]
// ---------------------------------------------------------------------------
__device__ __forceinline__ void split1(float x, __nv_bfloat16& h, __nv_bfloat16& l) {
    h = __float2bfloat16(x);
    l = __float2bfloat16(x - __bfloat162float(h));
}

__global__ void split_wt_kernel(const float* __restrict__ w, __nv_bfloat16* __restrict__ out) {
    int idx = blockIdx.x * blockDim.x + threadIdx.x;
    if (idx >= EE * EE / 4) return;
    int n = idx / (EE / 4), k4 = (idx % (EE / 4)) * 4;
    float4 v = ((const float4*)w)[idx];
    __nv_bfloat16 h[4], l[4];
    split1(v.x, h[0], l[0]); split1(v.y, h[1], l[1]);
    split1(v.z, h[2], l[2]); split1(v.w, h[3], l[3]);
    __nv_bfloat16* o = out + (long)n * KP;
    *(uint2*)(o + k4)          = *(uint2*)h;
    *(uint2*)(o + EE + k4)     = *(uint2*)h;
    *(uint2*)(o + 2 * EE + k4) = *(uint2*)l;
}

__global__ void split_act_kernel(const float* __restrict__ a, __nv_bfloat16* __restrict__ out) {
    int idx = blockIdx.x * blockDim.x + threadIdx.x;
    if (idx >= MM * EE / 4) return;
    int m = idx / (EE / 4), k4 = (idx % (EE / 4)) * 4;
    float4 v = ((const float4*)a)[idx];
    __nv_bfloat16 h[4], l[4];
    split1(v.x, h[0], l[0]); split1(v.y, h[1], l[1]);
    split1(v.z, h[2], l[2]); split1(v.w, h[3], l[3]);
    __nv_bfloat16* o = out + (long)m * KP;
    *(uint2*)(o + k4)          = *(uint2*)h;
    *(uint2*)(o + EE + k4)     = *(uint2*)l;
    *(uint2*)(o + 2 * EE + k4) = *(uint2*)h;
}

__global__ void im2col_split_kernel(const float* __restrict__ x, __nv_bfloat16* __restrict__ out) {
    int idx = blockIdx.x * blockDim.x + threadIdx.x;   // per 2 elems
    if (idx >= MM * EE / 2) return;
    int e2 = idx % (EE / 2);
    int s  = (idx / (EE / 2)) % SS;
    int b  = idx / ((EE / 2) * SS);
    int e  = e2 * 2;
    int c = e >> 8, r = e & 255, py = r >> 4, px = r & 15;
    int gy = s / GG, gx = s % GG;
    const float* xp = x + (((long)(b * 3 + c) * 224) + gy * PP + py) * 224 + gx * PP + px;
    float2 v = *(const float2*)xp;
    __nv_bfloat16 h[2], l[2];
    split1(v.x, h[0], l[0]); split1(v.y, h[1], l[1]);
    __nv_bfloat16* o = out + (long)(b * SS + s) * KP;
    *(uint32_t*)(o + e)          = *(uint32_t*)h;
    *(uint32_t*)(o + EE + e)     = *(uint32_t*)l;
    *(uint32_t*)(o + 2 * EE + e) = *(uint32_t*)h;
}

// ---------------------------------------------------------------------------
// LayerNorm over (S,E) per image
// ---------------------------------------------------------------------------
__global__ void ln_reduce_kernel(const float* __restrict__ in, float* __restrict__ stats) {
    int b = blockIdx.x;
    const float4* p = (const float4*)(in + (long)b * SE);
    float s = 0.f, s2 = 0.f;
    for (int i = threadIdx.x; i < SE / 4; i += blockDim.x) {
        float4 v = p[i];
        s  += v.x + v.y + v.z + v.w;
        s2 += v.x * v.x + v.y * v.y + v.z * v.z + v.w * v.w;
    }
    __shared__ float sh[256], sh2[256];
    sh[threadIdx.x] = s; sh2[threadIdx.x] = s2;
    __syncthreads();
    for (int st = 128; st > 0; st >>= 1) {
        if (threadIdx.x < st) {
            sh[threadIdx.x]  += sh[threadIdx.x + st];
            sh2[threadIdx.x] += sh2[threadIdx.x + st];
        }
        __syncthreads();
    }
    if (threadIdx.x == 0) {
        float mu  = sh[0] / (float)SE;
        float var = sh2[0] / (float)SE - mu * mu;
        stats[b * 2 + 0] = mu;
        stats[b * 2 + 1] = rsqrtf(var + 1e-5f);
    }
}

__global__ void ln_apply_kernel(const float* __restrict__ in, const float* __restrict__ stats,
                                const float* __restrict__ w, const float* __restrict__ bw,
                                float* __restrict__ out) {
    int i4 = blockIdx.x * blockDim.x + threadIdx.x;
    if (i4 >= (MM * EE) / 4) return;
    int b = i4 / (SE / 4), se4 = i4 - b * (SE / 4);
    float mu = stats[b * 2 + 0], rs = stats[b * 2 + 1];
    float4 v  = ((const float4*)in)[i4];
    float4 wv = ((const float4*)w)[se4];
    float4 bv = ((const float4*)bw)[se4];
    float4 o;
    o.x = (v.x - mu) * rs * wv.x + bv.x;
    o.y = (v.y - mu) * rs * wv.y + bv.y;
    o.z = (v.z - mu) * rs * wv.z + bv.z;
    o.w = (v.w - mu) * rs * wv.w + bv.w;
    ((float4*)out)[i4] = o;
}

__global__ void ln_apply_split_kernel(const float* __restrict__ in, const float* __restrict__ stats,
                                      const float* __restrict__ w, const float* __restrict__ bw,
                                      __nv_bfloat16* __restrict__ out) {
    int i4 = blockIdx.x * blockDim.x + threadIdx.x;
    if (i4 >= (MM * EE) / 4) return;
    int b = i4 / (SE / 4), se4 = i4 - b * (SE / 4);
    int m = i4 / (EE / 4), k4 = (i4 % (EE / 4)) * 4;
    float mu = stats[b * 2 + 0], rs = stats[b * 2 + 1];
    float4 v  = ((const float4*)in)[i4];
    float4 wv = ((const float4*)w)[se4];
    float4 bv = ((const float4*)bw)[se4];
    float y[4];
    y[0] = (v.x - mu) * rs * wv.x + bv.x;
    y[1] = (v.y - mu) * rs * wv.y + bv.y;
    y[2] = (v.z - mu) * rs * wv.z + bv.z;
    y[3] = (v.w - mu) * rs * wv.w + bv.w;
    __nv_bfloat16 h[4], l[4];
    split1(y[0], h[0], l[0]); split1(y[1], h[1], l[1]);
    split1(y[2], h[2], l[2]); split1(y[3], h[3], l[3]);
    __nv_bfloat16* o = out + (long)m * KP;
    *(uint2*)(o + k4)          = *(uint2*)h;
    *(uint2*)(o + EE + k4)     = *(uint2*)l;
    *(uint2*)(o + 2 * EE + k4) = *(uint2*)h;
}

// ---------------------------------------------------------------------------
// fp32 SGEMM (attention): C = scale * A * op(B); batched
// ---------------------------------------------------------------------------
#define BM 128
#define BN 64
#define BK 16
template <bool TRANS_B>
__global__ void __launch_bounds__(256)
gemm_kernel(const float* __restrict__ A, const float* __restrict__ Bm,
            float* __restrict__ C,
            int Md, int Nd, int Kd, int lda, int ldb, int ldc,
            int Hdiv, long sA1, long sA2, long sB1, long sB2, long sC1, long sC2,
            float scale)
{
    __shared__ float As[BK][BM];
    __shared__ float Bs[BK][BN];
    int z = blockIdx.z, z1 = z / Hdiv, z2 = z % Hdiv;
    A  += z1 * sA1 + z2 * sA2;
    Bm += z1 * sB1 + z2 * sB2;
    C  += z1 * sC1 + z2 * sC2;

    int tid = threadIdx.x, tx = tid & 15, ty = tid >> 4;
    int m0 = blockIdx.x * BM, n0 = blockIdx.y * BN;
    float acc[8][4];
#pragma unroll
    for (int i = 0; i < 8; i++)
#pragma unroll
        for (int j = 0; j < 4; j++) acc[i][j] = 0.0f;

    for (int k0 = 0; k0 < Kd; k0 += BK) {
#pragma unroll
        for (int i = 0; i < 2; i++) {
            int f4 = tid + i * 256, m = f4 >> 2, kf = (f4 & 3) * 4;
            int gm = m0 + m, gk = k0 + kf;
            float4 v = make_float4(0.f, 0.f, 0.f, 0.f);
            if (gm < Md) {
                if (gk + 3 < Kd) v = *(const float4*)(A + (long)gm * lda + gk);
                else {
                    v.x = (gk+0 < Kd) ? A[(long)gm*lda+gk+0] : 0.f;
                    v.y = (gk+1 < Kd) ? A[(long)gm*lda+gk+1] : 0.f;
                    v.z = (gk+2 < Kd) ? A[(long)gm*lda+gk+2] : 0.f;
                    v.w = (gk+3 < Kd) ? A[(long)gm*lda+gk+3] : 0.f;
                }
            }
            As[kf+0][m] = v.x; As[kf+1][m] = v.y; As[kf+2][m] = v.z; As[kf+3][m] = v.w;
        }
        if (TRANS_B) {
            int n = tid >> 2, kf = (tid & 3) * 4;
            int gn = n0 + n, gk = k0 + kf;
            float4 v = make_float4(0.f, 0.f, 0.f, 0.f);
            if (gn < Nd) {
                if (gk + 3 < Kd) v = *(const float4*)(Bm + (long)gn * ldb + gk);
                else {
                    v.x = (gk+0 < Kd) ? Bm[(long)gn*ldb+gk+0] : 0.f;
                    v.y = (gk+1 < Kd) ? Bm[(long)gn*ldb+gk+1] : 0.f;
                    v.z = (gk+2 < Kd) ? Bm[(long)gn*ldb+gk+2] : 0.f;
                    v.w = (gk+3 < Kd) ? Bm[(long)gn*ldb+gk+3] : 0.f;
                }
            }
            Bs[kf+0][n] = v.x; Bs[kf+1][n] = v.y; Bs[kf+2][n] = v.z; Bs[kf+3][n] = v.w;
        } else {
            int k = tid >> 4, nf = (tid & 15) * 4;
            int gk = k0 + k, gn = n0 + nf;
            float4 v = make_float4(0.f, 0.f, 0.f, 0.f);
            if (gk < Kd) {
                if (gn + 3 < Nd) v = *(const float4*)(Bm + (long)gk * ldb + gn);
                else {
                    v.x = (gn+0 < Nd) ? Bm[(long)gk*ldb+gn+0] : 0.f;
                    v.y = (gn+1 < Nd) ? Bm[(long)gk*ldb+gn+1] : 0.f;
                    v.z = (gn+2 < Nd) ? Bm[(long)gk*ldb+gn+2] : 0.f;
                    v.w = (gn+3 < Nd) ? Bm[(long)gk*ldb+gn+3] : 0.f;
                }
            }
            *(float4*)&Bs[k][nf] = v;
        }
        __syncthreads();
#pragma unroll
        for (int k = 0; k < BK; k++) {
            float a[8], b[4];
#pragma unroll
            for (int i = 0; i < 8; i++) a[i] = As[k][ty * 8 + i];
#pragma unroll
            for (int j = 0; j < 4; j++) b[j] = Bs[k][tx * 4 + j];
#pragma unroll
            for (int i = 0; i < 8; i++)
#pragma unroll
                for (int j = 0; j < 4; j++) acc[i][j] += a[i] * b[j];
        }
        __syncthreads();
    }
#pragma unroll
    for (int i = 0; i < 8; i++) {
        int gm = m0 + ty * 8 + i;
        if (gm >= Md) continue;
#pragma unroll
        for (int j = 0; j < 4; j++) {
            int gn = n0 + tx * 4 + j;
            if (gn >= Nd) continue;
            C[(long)gm * ldc + gn] = acc[i][j] * scale;
        }
    }
}

// ---------------------------------------------------------------------------
// softmax over last dim (196), one warp per row
// ---------------------------------------------------------------------------
__global__ void softmax_kernel(float* __restrict__ sc, int rows, int cols) {
    int warp = threadIdx.x >> 5, lane = threadIdx.x & 31;
    int row = blockIdx.x * 4 + warp;
    if (row >= rows) return;
    float* p = sc + (long)row * cols;
    float v[7];
    float mx = -1e30f;
#pragma unroll
    for (int i = 0; i < 7; i++) {
        int idx = lane + i * 32;
        v[i] = (idx < cols) ? p[idx] : -1e30f;
        mx = fmaxf(mx, v[i]);
    }
#pragma unroll
    for (int o = 16; o > 0; o >>= 1) mx = fmaxf(mx, __shfl_xor_sync(0xFFFFFFFFu, mx, o));
    float sum = 0.f;
#pragma unroll
    for (int i = 0; i < 7; i++) { v[i] = expf(v[i] - mx); sum += v[i]; }
#pragma unroll
    for (int o = 16; o > 0; o >>= 1) sum += __shfl_xor_sync(0xFFFFFFFFu, sum, o);
    float inv = 1.0f / sum;
#pragma unroll
    for (int i = 0; i < 7; i++) {
        int idx = lane + i * 32;
        if (idx < cols) p[idx] = v[i] * inv;
    }
}

// ---------------------------------------------------------------------------
extern "C" void kernel_launch(void* const* d_in, const int* in_sizes, int n_in,
                              void* d_out, int out_size) {
    const float* x      = (const float*)d_in[0];
    const float* conv_w = (const float*)d_in[1];
    const float* conv_b = (const float*)d_in[2];
    const float* wq = (const float*)d_in[3];
    const float* bq = (const float*)d_in[4];
    const float* wk = (const float*)d_in[5];
    const float* bk = (const float*)d_in[6];
    const float* wv = (const float*)d_in[7];
    const float* bv = (const float*)d_in[8];
    const float* wo = (const float*)d_in[9];
    const float* bo = (const float*)d_in[10];
    const float* ln1w = (const float*)d_in[11];
    const float* ln1b = (const float*)d_in[12];
    const float* ln2w = (const float*)d_in[13];
    const float* ln2b = (const float*)d_in[14];
    float* out = (float*)d_out;

    float *emb, *q, *k, *v, *att, *res, *scores, *st1, *st2;
    __nv_bfloat16 *a16, *w16;
    cudaGetSymbolAddress((void**)&emb,    g_emb);
    cudaGetSymbolAddress((void**)&q,      g_q);
    cudaGetSymbolAddress((void**)&k,      g_k);
    cudaGetSymbolAddress((void**)&v,      g_v);
    cudaGetSymbolAddress((void**)&att,    g_att);
    cudaGetSymbolAddress((void**)&res,    g_res);
    cudaGetSymbolAddress((void**)&scores, g_scores);
    cudaGetSymbolAddress((void**)&st1,    g_stats1);
    cudaGetSymbolAddress((void**)&st2,    g_stats2);
    cudaGetSymbolAddress((void**)&a16,    g_a16);
    cudaGetSymbolAddress((void**)&w16,    g_w16);

    const int total = MM * EE;
    const size_t wstride = (size_t)EE * KP;
    const dim3 tc_grid(MM / 128, EE / 128);   // 98 x 6
    const float scale = 1.0f / sqrtf((float)HDIM);

    // 0. split weights
    const int wthreads = EE * EE / 4;
    split_wt_kernel<<<(wthreads + 255) / 256, 256>>>(conv_w, w16 + 0 * wstride);
    split_wt_kernel<<<(wthreads + 255) / 256, 256>>>(wq,     w16 + 1 * wstride);
    split_wt_kernel<<<(wthreads + 255) / 256, 256>>>(wk,     w16 + 2 * wstride);
    split_wt_kernel<<<(wthreads + 255) / 256, 256>>>(wv,     w16 + 3 * wstride);
    split_wt_kernel<<<(wthreads + 255) / 256, 256>>>(wo,     w16 + 4 * wstride);

    // 1. im2col + split
    im2col_split_kernel<<<(total / 2 + 255) / 256, 256>>>(x, a16);

    // 2. patch embed (HMMA)
    hmma_gemm_kernel<<<tc_grid, 256>>>(a16, w16 + 0 * wstride, conv_b, nullptr, emb);

    // 3. LN1 -> split
    ln_reduce_kernel<<<BB, 256>>>(emb, st1);
    ln_apply_split_kernel<<<(total / 4 + 255) / 256, 256>>>(emb, st1, ln1w, ln1b, a16);

    // 4. QKV (HMMA)
    hmma_gemm_kernel<<<tc_grid, 256>>>(a16, w16 + 1 * wstride, bq, nullptr, q);
    hmma_gemm_kernel<<<tc_grid, 256>>>(a16, w16 + 2 * wstride, bk, nullptr, k);
    hmma_gemm_kernel<<<tc_grid, 256>>>(a16, w16 + 3 * wstride, bv, nullptr, v);

    // 5. scores = scale * Q @ K^T (batched fp32)
    gemm_kernel<true><<<dim3(2, 4, BB * HH), 256>>>(q, k, scores,
        SS, SS, HDIM, EE, EE, SS,
        HH, (long)SE, (long)HDIM, (long)SE, (long)HDIM,
        (long)HH * SS * SS, (long)SS * SS, scale);

    // 6. softmax
    softmax_kernel<<<(BB * HH * SS) / 4, 128>>>(scores, BB * HH * SS, SS);

    // 7. O = attn @ V (batched fp32 NN)
    gemm_kernel<false><<<dim3(2, 3, BB * HH), 256>>>(scores, v, att,
        SS, HDIM, SS, SS, EE, EE,
        HH, (long)HH * SS * SS, (long)SS * SS, (long)SE, (long)HDIM,
        (long)SE, (long)HDIM, 1.0f);

    // 8. split att ; out proj + residual (HMMA)
    split_act_kernel<<<(total / 4 + 255) / 256, 256>>>(att, a16);
    hmma_gemm_kernel<<<tc_grid, 256>>>(a16, w16 + 4 * wstride, bo, emb, res);

    // 9. LN2 -> out
    ln_reduce_kernel<<<BB, 256>>>(res, st2);
    ln_apply_kernel<<<(total / 4 + 255) / 256, 256>>>(res, st2, ln2w, ln2b, out);
}

// round 6
// speedup vs baseline: 3.9855x; 1.1247x over previous
#include <cuda_runtime.h>
#include <cuda_bf16.h>
#include <cstdint>
#include <math.h>

// ---------------------------------------------------------------------------
// ViT block, R6 (= R4 candidate; R4/R5 were broker timeouts, never ran).
// Everything-matmul on mma.sync bf16 with bf16x3 splits.
// Main GEMMs: 128x128x32 fixed-size kernel, epilogue writes split layouts for
// QKV. Attention: batched HMMA (scores, attnV) + split-emitting softmax.
// ---------------------------------------------------------------------------

#define BB   64
#define SS   196
#define EE   768
#define HH   4
#define HDIM 192
#define PP   16
#define GG   14
#define MM   (BB * SS)        // 12544
#define SE   (SS * EE)        // 150528
#define KP   (3 * EE)         // 2304
#define NKC  (KP / 32)        // 72
#define KQK  (3 * HDIM)       // 576   scores split-K
#define KPV  608              // 588 padded to 608  attnV split-K
#define ZZ   (BB * HH)        // 256 batched heads

// ---------------- scratch ---------------------------------------------------
__device__ float g_emb[MM * EE];
__device__ float g_res[MM * EE];
__device__ float g_scores[(size_t)ZZ * SS * SS];
__device__ float g_stats1[BB * 2];
__device__ float g_stats2[BB * 2];
__device__ __nv_bfloat16 g_a16[(size_t)MM * KP];
__device__ __nv_bfloat16 g_w16[5][(size_t)EE * KP];
__device__ __nv_bfloat16 g_qs[(size_t)ZZ * SS * KQK];
__device__ __nv_bfloat16 g_ks[(size_t)ZZ * SS * KQK];
__device__ __nv_bfloat16 g_vt[(size_t)ZZ * HDIM * KPV];
__device__ __nv_bfloat16 g_p [(size_t)ZZ * SS * KPV];

// ---------------- helpers ---------------------------------------------------
__device__ __forceinline__ uint32_t smem_u32(const void* p) {
    uint32_t a;
    asm("{ .reg .u64 t; cvta.to.shared.u64 t, %1; cvt.u32.u64 %0, t; }" : "=r"(a) : "l"(p));
    return a;
}
__device__ __forceinline__ void cp16(uint32_t saddr, const void* g) {
    asm volatile("cp.async.cg.shared.global [%0], [%1], 16;"
                 :: "r"(saddr), "l"(__cvta_generic_to_global(g)));
}
#define CP_COMMIT() asm volatile("cp.async.commit_group;" ::: "memory")
#define CP_WAIT1()  asm volatile("cp.async.wait_group 1;" ::: "memory")
#define CP_WAIT0()  asm volatile("cp.async.wait_group 0;" ::: "memory")

__device__ __forceinline__ void ldm_x4(uint32_t* r, uint32_t addr) {
    asm volatile("ldmatrix.sync.aligned.m8n8.x4.shared.b16 {%0,%1,%2,%3}, [%4];"
                 : "=r"(r[0]), "=r"(r[1]), "=r"(r[2]), "=r"(r[3]) : "r"(addr));
}
__device__ __forceinline__ void mma16816(float* c, const uint32_t* a, uint32_t b0, uint32_t b1) {
    asm volatile("mma.sync.aligned.m16n8k16.row.col.f32.bf16.bf16.f32 "
                 "{%0,%1,%2,%3}, {%4,%5,%6,%7}, {%8,%9}, {%0,%1,%2,%3};"
                 : "+f"(c[0]), "+f"(c[1]), "+f"(c[2]), "+f"(c[3])
                 : "r"(a[0]), "r"(a[1]), "r"(a[2]), "r"(a[3]), "r"(b0), "r"(b1));
}
__device__ __forceinline__ uint32_t pack2(float x, float y) {
    __nv_bfloat162 t = __floats2bfloat162_rn(x, y);
    return *(uint32_t*)&t;
}
__device__ __forceinline__ float lopart(float x) {
    return x - __bfloat162float(__float2bfloat16(x));
}

// common inner-compute macro (expects sA, sB, acc, lane constants defined)
#define MMA_TILE_COMPUTE()                                                     \
    _Pragma("unroll")                                                          \
    for (int ks = 0; ks < 2; ks++) {                                           \
        const int k2 = ks * 2;                                                 \
        uint32_t a[4][4], b[2][4];                                             \
        _Pragma("unroll")                                                      \
        for (int mt = 0; mt < 4; mt++) {                                       \
            int row = wm * 64 + mt * 16 + rA;                                  \
            ldm_x4(a[mt], sA + row * 64 + (((k2 + chA) ^ selA) << 4));         \
        }                                                                      \
        _Pragma("unroll")                                                      \
        for (int p = 0; p < 2; p++) {                                          \
            int row = wn * 32 + p * 16 + rB;                                   \
            ldm_x4(b[p], sB + row * 64 + (((k2 + chB) ^ selB) << 4));          \
        }                                                                      \
        _Pragma("unroll")                                                      \
        for (int mt = 0; mt < 4; mt++)                                         \
            _Pragma("unroll")                                                  \
            for (int nt = 0; nt < 4; nt++)                                     \
                mma16816(acc[mt][nt], a[mt],                                   \
                         b[nt >> 1][(nt & 1) * 2], b[nt >> 1][(nt & 1) * 2 + 1]); \
    }

// ---------------------------------------------------------------------------
// Main HMMA GEMM: [MM,KP] x [768,KP]^T, tile 128x128x32.
// EPI: 0 = fp32 C (+bias, opt resid); 1 = Q split [hi|lo|hi]; 2 = K split
// [hi|hi|lo]; 3 = Vt transposed split [Vh|Vh|Vl] (K padded to KPV).
// ---------------------------------------------------------------------------
template <int EPI>
__global__ void __launch_bounds__(256, 2)
hmma_main_kernel(const __nv_bfloat16* __restrict__ A, const __nv_bfloat16* __restrict__ Bw,
                 const float* __restrict__ bias, const float* __restrict__ resid,
                 float* __restrict__ C, __nv_bfloat16* __restrict__ O16)
{
    __shared__ __align__(1024) char smem[32768];
    const uint32_t sb = smem_u32(smem);
    const int tid = threadIdx.x;
    const int lane = tid & 31, wid = tid >> 5;
    const int wm = wid & 1, wn = wid >> 1;
    const int m0 = blockIdx.x * 128, n0 = blockIdx.y * 128;

    const __nv_bfloat16* Abase = A + (long)m0 * KP;
    const __nv_bfloat16* Bbase = Bw + (long)n0 * KP;

#define LOAD_STAGE(buf, kc) do {                                              \
        int _ko = (kc) * 32;                                                  \
        _Pragma("unroll")                                                     \
        for (int _i = 0; _i < 2; _i++) {                                      \
            int _lin = tid + _i * 256;                                        \
            int _row = _lin >> 2, _ch = _lin & 3;                             \
            uint32_t _sw = (uint32_t)(_row * 64 + ((_ch ^ ((_row >> 1) & 3)) << 4)); \
            cp16(sb + (buf) * 8192 + _sw,         Abase + (long)_row * KP + _ko + _ch * 8); \
            cp16(sb + 16384 + (buf) * 8192 + _sw, Bbase + (long)_row * KP + _ko + _ch * 8); \
        }                                                                     \
    } while (0)

    float acc[4][4][4] = {};
    const int g = lane >> 3, r8 = lane & 7;
    const int rA = (g & 1) * 8 + r8, selA = (rA >> 1) & 3, chA = g >> 1;
    const int rB = (g >> 1) * 8 + r8, selB = (rB >> 1) & 3, chB = g & 1;

    LOAD_STAGE(0, 0); CP_COMMIT();
    LOAD_STAGE(1, 1); CP_COMMIT();

    for (int kc = 0; kc < NKC; kc++) {
        const int buf = kc & 1;
        if (kc < NKC - 2) CP_WAIT1(); else CP_WAIT0();
        __syncthreads();
        const uint32_t sA = sb + buf * 8192;
        const uint32_t sB = sb + 16384 + buf * 8192;
        MMA_TILE_COMPUTE();
        __syncthreads();
        if (kc + 2 < NKC) { LOAD_STAGE(buf, kc + 2); CP_COMMIT(); }
    }
#undef LOAD_STAGE

#pragma unroll
    for (int mt = 0; mt < 4; mt++) {
#pragma unroll
        for (int half = 0; half < 2; half++) {
            const int gm = m0 + wm * 64 + mt * 16 + (lane >> 2) + half * 8;
#pragma unroll
            for (int nt = 0; nt < 4; nt++) {
                const int gn = n0 + wn * 32 + nt * 8 + (lane & 3) * 2;
                const float c0 = acc[mt][nt][half * 2 + 0];
                const float c1 = acc[mt][nt][half * 2 + 1];
                if (EPI == 0) {
                    float v0 = c0 + bias[gn], v1 = c1 + bias[gn + 1];
                    if (resid) {
                        float2 r = *(const float2*)(resid + (long)gm * EE + gn);
                        v0 += r.x; v1 += r.y;
                    }
                    *(float2*)(C + (long)gm * EE + gn) = make_float2(v0, v1);
                } else {
                    float y0 = c0 + bias[gn], y1 = c1 + bias[gn + 1];
                    const int b = gm / SS, s = gm - b * SS;
                    const int h = gn / HDIM, d = gn - h * HDIM;
                    uint32_t hi = pack2(y0, y1);
                    uint32_t lo = pack2(lopart(y0), lopart(y1));
                    if (EPI == 1) {         // Q: [hi | lo | hi]
                        __nv_bfloat16* o = O16 + ((long)(b * HH + h) * SS + s) * KQK + d;
                        *(uint32_t*)(o)              = hi;
                        *(uint32_t*)(o + HDIM)       = lo;
                        *(uint32_t*)(o + 2 * HDIM)   = hi;
                    } else if (EPI == 2) {  // K: [hi | hi | lo]
                        __nv_bfloat16* o = O16 + ((long)(b * HH + h) * SS + s) * KQK + d;
                        *(uint32_t*)(o)              = hi;
                        *(uint32_t*)(o + HDIM)       = hi;
                        *(uint32_t*)(o + 2 * HDIM)   = lo;
                    } else {                // Vt: rows d, cols s : [Vh | Vh | Vl]
                        __nv_bfloat16* o = O16 + ((long)(b * HH + h) * HDIM + d) * KPV + s;
                        __nv_bfloat16 h0 = __float2bfloat16(y0), h1 = __float2bfloat16(y1);
                        __nv_bfloat16 l0 = __float2bfloat16(lopart(y0)), l1 = __float2bfloat16(lopart(y1));
                        o[0] = h0;  o[SS] = h0;  o[2 * SS] = l0;
                        o += KPV;   // d+1
                        o[0] = h1;  o[SS] = h1;  o[2 * SS] = l1;
                    }
                }
            }
        }
    }
}

// ---------------------------------------------------------------------------
// Batched HMMA GEMM (NT): per z, C = scale * A[Md,Kd] . B[Nd,Kd]^T
// Row-clamped loads; bounds-checked stores. EPI 0: fp32 C (z-strided).
// EPI 1: split-act out into a16 [hi|lo|hi] at row z1*SS+gm, col z2*HDIM+gn.
// ---------------------------------------------------------------------------
template <int EPI>
__global__ void __launch_bounds__(256, 2)
hmma_bat_kernel(const __nv_bfloat16* __restrict__ Ag, const __nv_bfloat16* __restrict__ Bg,
                float* __restrict__ C, __nv_bfloat16* __restrict__ O16,
                int Md, int Nd, int Kd, long sA, long sB,
                int Hdiv, long sC1, long sC2, int ldc, float scale)
{
    __shared__ __align__(1024) char smem[32768];
    const uint32_t sb = smem_u32(smem);
    const int tid = threadIdx.x;
    const int lane = tid & 31, wid = tid >> 5;
    const int wm = wid & 1, wn = wid >> 1;
    const int m0 = blockIdx.x * 128, n0 = blockIdx.y * 128;
    const int z = blockIdx.z;
    const int z1 = z / Hdiv, z2 = z - z1 * Hdiv;

    const __nv_bfloat16* Abase = Ag + (long)z * sA;
    const __nv_bfloat16* Bbase = Bg + (long)z * sB;
    const int nkc = Kd >> 5;

#define LOAD_STAGE_B(buf, kc) do {                                            \
        int _ko = (kc) * 32;                                                  \
        _Pragma("unroll")                                                     \
        for (int _i = 0; _i < 2; _i++) {                                      \
            int _lin = tid + _i * 256;                                        \
            int _row = _lin >> 2, _ch = _lin & 3;                             \
            uint32_t _sw = (uint32_t)(_row * 64 + ((_ch ^ ((_row >> 1) & 3)) << 4)); \
            int _ra = min(m0 + _row, Md - 1);                                 \
            int _rb = min(n0 + _row, Nd - 1);                                 \
            cp16(sb + (buf) * 8192 + _sw,         Abase + (long)_ra * Kd + _ko + _ch * 8); \
            cp16(sb + 16384 + (buf) * 8192 + _sw, Bbase + (long)_rb * Kd + _ko + _ch * 8); \
        }                                                                     \
    } while (0)

    float acc[4][4][4] = {};
    const int g = lane >> 3, r8 = lane & 7;
    const int rA = (g & 1) * 8 + r8, selA = (rA >> 1) & 3, chA = g >> 1;
    const int rB = (g >> 1) * 8 + r8, selB = (rB >> 1) & 3, chB = g & 1;

    LOAD_STAGE_B(0, 0); CP_COMMIT();
    LOAD_STAGE_B(1, 1); CP_COMMIT();

    for (int kc = 0; kc < nkc; kc++) {
        const int buf = kc & 1;
        if (kc < nkc - 2) CP_WAIT1(); else CP_WAIT0();
        __syncthreads();
        const uint32_t sA = sb + buf * 8192;
        const uint32_t sB = sb + 16384 + buf * 8192;
        MMA_TILE_COMPUTE();
        __syncthreads();
        if (kc + 2 < nkc) { LOAD_STAGE_B(buf, kc + 2); CP_COMMIT(); }
    }
#undef LOAD_STAGE_B

    float* Cz = (EPI == 0) ? (C + (long)z1 * sC1 + (long)z2 * sC2) : nullptr;
#pragma unroll
    for (int mt = 0; mt < 4; mt++) {
#pragma unroll
        for (int half = 0; half < 2; half++) {
            const int gm = m0 + wm * 64 + mt * 16 + (lane >> 2) + half * 8;
            if (gm >= Md) continue;
#pragma unroll
            for (int nt = 0; nt < 4; nt++) {
                const int gn = n0 + wn * 32 + nt * 8 + (lane & 3) * 2;
                if (gn >= Nd) continue;
                const float c0 = acc[mt][nt][half * 2 + 0] * scale;
                const float c1 = acc[mt][nt][half * 2 + 1] * scale;
                if (EPI == 0) {
                    *(float2*)(Cz + (long)gm * ldc + gn) = make_float2(c0, c1);
                } else {
                    const long row = (long)z1 * SS + gm;
                    const int  col = z2 * HDIM + gn;
                    __nv_bfloat16* o = O16 + row * KP + col;
                    *(uint32_t*)(o)          = pack2(c0, c1);
                    *(uint32_t*)(o + EE)     = pack2(lopart(c0), lopart(c1));
                    *(uint32_t*)(o + 2 * EE) = pack2(c0, c1);
                }
            }
        }
    }
}

// ---------------------------------------------------------------------------
// splits / im2col / LN / softmax
// ---------------------------------------------------------------------------
__device__ __forceinline__ void split1(float x, __nv_bfloat16& h, __nv_bfloat16& l) {
    h = __float2bfloat16(x);
    l = __float2bfloat16(x - __bfloat162float(h));
}

__global__ void split_wt_kernel(const float* __restrict__ w, __nv_bfloat16* __restrict__ out) {
    int idx = blockIdx.x * blockDim.x + threadIdx.x;
    if (idx >= EE * EE / 4) return;
    int n = idx / (EE / 4), k4 = (idx % (EE / 4)) * 4;
    float4 v = ((const float4*)w)[idx];
    __nv_bfloat16 h[4], l[4];
    split1(v.x, h[0], l[0]); split1(v.y, h[1], l[1]);
    split1(v.z, h[2], l[2]); split1(v.w, h[3], l[3]);
    __nv_bfloat16* o = out + (long)n * KP;
    *(uint2*)(o + k4)          = *(uint2*)h;
    *(uint2*)(o + EE + k4)     = *(uint2*)h;
    *(uint2*)(o + 2 * EE + k4) = *(uint2*)l;
}

__global__ void im2col_split_kernel(const float* __restrict__ x, __nv_bfloat16* __restrict__ out) {
    int idx = blockIdx.x * blockDim.x + threadIdx.x;
    if (idx >= MM * EE / 2) return;
    int e2 = idx % (EE / 2);
    int s  = (idx / (EE / 2)) % SS;
    int b  = idx / ((EE / 2) * SS);
    int e  = e2 * 2;
    int c = e >> 8, r = e & 255, py = r >> 4, px = r & 15;
    int gy = s / GG, gx = s % GG;
    const float* xp = x + (((long)(b * 3 + c) * 224) + gy * PP + py) * 224 + gx * PP + px;
    float2 v = *(const float2*)xp;
    __nv_bfloat16 h[2], l[2];
    split1(v.x, h[0], l[0]); split1(v.y, h[1], l[1]);
    __nv_bfloat16* o = out + (long)(b * SS + s) * KP;
    *(uint32_t*)(o + e)          = *(uint32_t*)h;
    *(uint32_t*)(o + EE + e)     = *(uint32_t*)l;
    *(uint32_t*)(o + 2 * EE + e) = *(uint32_t*)h;
}

__global__ void ln_reduce_kernel(const float* __restrict__ in, float* __restrict__ stats) {
    int b = blockIdx.x;
    const float4* p = (const float4*)(in + (long)b * SE);
    float s = 0.f, s2 = 0.f;
    for (int i = threadIdx.x; i < SE / 4; i += blockDim.x) {
        float4 v = p[i];
        s  += v.x + v.y + v.z + v.w;
        s2 += v.x * v.x + v.y * v.y + v.z * v.z + v.w * v.w;
    }
    __shared__ float sh[256], sh2[256];
    sh[threadIdx.x] = s; sh2[threadIdx.x] = s2;
    __syncthreads();
    for (int st = 128; st > 0; st >>= 1) {
        if (threadIdx.x < st) {
            sh[threadIdx.x]  += sh[threadIdx.x + st];
            sh2[threadIdx.x] += sh2[threadIdx.x + st];
        }
        __syncthreads();
    }
    if (threadIdx.x == 0) {
        float mu  = sh[0] / (float)SE;
        float var = sh2[0] / (float)SE - mu * mu;
        stats[b * 2 + 0] = mu;
        stats[b * 2 + 1] = rsqrtf(var + 1e-5f);
    }
}

__global__ void ln_apply_kernel(const float* __restrict__ in, const float* __restrict__ stats,
                                const float* __restrict__ w, const float* __restrict__ bw,
                                float* __restrict__ out) {
    int i4 = blockIdx.x * blockDim.x + threadIdx.x;
    if (i4 >= (MM * EE) / 4) return;
    int b = i4 / (SE / 4), se4 = i4 - b * (SE / 4);
    float mu = stats[b * 2 + 0], rs = stats[b * 2 + 1];
    float4 v  = ((const float4*)in)[i4];
    float4 wv = ((const float4*)w)[se4];
    float4 bv = ((const float4*)bw)[se4];
    float4 o;
    o.x = (v.x - mu) * rs * wv.x + bv.x;
    o.y = (v.y - mu) * rs * wv.y + bv.y;
    o.z = (v.z - mu) * rs * wv.z + bv.z;
    o.w = (v.w - mu) * rs * wv.w + bv.w;
    ((float4*)out)[i4] = o;
}

__global__ void ln_apply_split_kernel(const float* __restrict__ in, const float* __restrict__ stats,
                                      const float* __restrict__ w, const float* __restrict__ bw,
                                      __nv_bfloat16* __restrict__ out) {
    int i4 = blockIdx.x * blockDim.x + threadIdx.x;
    if (i4 >= (MM * EE) / 4) return;
    int b = i4 / (SE / 4), se4 = i4 - b * (SE / 4);
    int m = i4 / (EE / 4), k4 = (i4 % (EE / 4)) * 4;
    float mu = stats[b * 2 + 0], rs = stats[b * 2 + 1];
    float4 v  = ((const float4*)in)[i4];
    float4 wv = ((const float4*)w)[se4];
    float4 bv = ((const float4*)bw)[se4];
    float y[4];
    y[0] = (v.x - mu) * rs * wv.x + bv.x;
    y[1] = (v.y - mu) * rs * wv.y + bv.y;
    y[2] = (v.z - mu) * rs * wv.z + bv.z;
    y[3] = (v.w - mu) * rs * wv.w + bv.w;
    __nv_bfloat16 h[4], l[4];
    split1(y[0], h[0], l[0]); split1(y[1], h[1], l[1]);
    split1(y[2], h[2], l[2]); split1(y[3], h[3], l[3]);
    __nv_bfloat16* o = out + (long)m * KP;
    *(uint2*)(o + k4)          = *(uint2*)h;
    *(uint2*)(o + EE + k4)     = *(uint2*)l;
    *(uint2*)(o + 2 * EE + k4) = *(uint2*)h;
}

// softmax over 196 cols; emits split-bf16 P [Ph | Pl | Ph] + zero pad.
__global__ void softmax_p_kernel(const float* __restrict__ sc, __nv_bfloat16* __restrict__ P) {
    int warp = threadIdx.x >> 5, lane = threadIdx.x & 31;
    long row = (long)blockIdx.x * 4 + warp;
    if (row >= (long)ZZ * SS) return;
    const float* p = sc + row * SS;
    float v[7];
    float mx = -1e30f;
#pragma unroll
    for (int i = 0; i < 7; i++) {
        int idx = lane + i * 32;
        v[i] = (idx < SS) ? p[idx] : -1e30f;
        mx = fmaxf(mx, v[i]);
    }
#pragma unroll
    for (int o = 16; o > 0; o >>= 1) mx = fmaxf(mx, __shfl_xor_sync(0xFFFFFFFFu, mx, o));
    float sum = 0.f;
#pragma unroll
    for (int i = 0; i < 7; i++) { v[i] = expf(v[i] - mx); sum += v[i]; }
#pragma unroll
    for (int o = 16; o > 0; o >>= 1) sum += __shfl_xor_sync(0xFFFFFFFFu, sum, o);
    float inv = 1.0f / sum;
    __nv_bfloat16* o = P + row * KPV;
#pragma unroll
    for (int i = 0; i < 7; i++) {
        int idx = lane + i * 32;
        if (idx < SS) {
            float y = v[i] * inv;
            __nv_bfloat16 h, l;
            split1(y, h, l);
            o[idx] = h; o[SS + idx] = l; o[2 * SS + idx] = h;
        }
    }
    if (lane < 20) o[3 * SS + lane] = __float2bfloat16(0.f);   // 588..607
}

// zero the pad columns (588..607) of Vt rows
__global__ void vt_pad_kernel(__nv_bfloat16* __restrict__ Vt) {
    int idx = blockIdx.x * blockDim.x + threadIdx.x;     // ZZ*HDIM*10 u32
    if (idx >= ZZ * HDIM * 10) return;
    int r = idx / 10, c = idx % 10;
    *(uint32_t*)(Vt + (long)r * KPV + 588 + c * 2) = 0u;
}

// ---------------------------------------------------------------------------
extern "C" void kernel_launch(void* const* d_in, const int* in_sizes, int n_in,
                              void* d_out, int out_size) {
    const float* x      = (const float*)d_in[0];
    const float* conv_w = (const float*)d_in[1];
    const float* conv_b = (const float*)d_in[2];
    const float* wq = (const float*)d_in[3];
    const float* bq = (const float*)d_in[4];
    const float* wk = (const float*)d_in[5];
    const float* bk = (const float*)d_in[6];
    const float* wv = (const float*)d_in[7];
    const float* bv = (const float*)d_in[8];
    const float* wo = (const float*)d_in[9];
    const float* bo = (const float*)d_in[10];
    const float* ln1w = (const float*)d_in[11];
    const float* ln1b = (const float*)d_in[12];
    const float* ln2w = (const float*)d_in[13];
    const float* ln2b = (const float*)d_in[14];
    float* out = (float*)d_out;

    float *emb, *res, *scores, *st1, *st2;
    __nv_bfloat16 *a16, *w16, *qs, *ks, *vt, *pp;
    cudaGetSymbolAddress((void**)&emb,    g_emb);
    cudaGetSymbolAddress((void**)&res,    g_res);
    cudaGetSymbolAddress((void**)&scores, g_scores);
    cudaGetSymbolAddress((void**)&st1,    g_stats1);
    cudaGetSymbolAddress((void**)&st2,    g_stats2);
    cudaGetSymbolAddress((void**)&a16,    g_a16);
    cudaGetSymbolAddress((void**)&w16,    g_w16);
    cudaGetSymbolAddress((void**)&qs,     g_qs);
    cudaGetSymbolAddress((void**)&ks,     g_ks);
    cudaGetSymbolAddress((void**)&vt,     g_vt);
    cudaGetSymbolAddress((void**)&pp,     g_p);

    const int total = MM * EE;
    const size_t wstride = (size_t)EE * KP;
    const dim3 mgrid(MM / 128, EE / 128);      // 98 x 6
    const float scale = 1.0f / sqrtf((float)HDIM);

    // 0. split weights
    const int wthreads = EE * EE / 4;
    split_wt_kernel<<<(wthreads + 255) / 256, 256>>>(conv_w, w16 + 0 * wstride);
    split_wt_kernel<<<(wthreads + 255) / 256, 256>>>(wq,     w16 + 1 * wstride);
    split_wt_kernel<<<(wthreads + 255) / 256, 256>>>(wk,     w16 + 2 * wstride);
    split_wt_kernel<<<(wthreads + 255) / 256, 256>>>(wv,     w16 + 3 * wstride);
    split_wt_kernel<<<(wthreads + 255) / 256, 256>>>(wo,     w16 + 4 * wstride);

    // 1. im2col + split
    im2col_split_kernel<<<(total / 2 + 255) / 256, 256>>>(x, a16);

    // 2. patch embed -> emb (fp32)
    hmma_main_kernel<0><<<mgrid, 256>>>(a16, w16 + 0 * wstride, conv_b, nullptr, emb, nullptr);

    // 3. LN1 -> split a16
    ln_reduce_kernel<<<BB, 256>>>(emb, st1);
    ln_apply_split_kernel<<<(total / 4 + 255) / 256, 256>>>(emb, st1, ln1w, ln1b, a16);

    // 4. QKV -> split per-head layouts directly
    hmma_main_kernel<1><<<mgrid, 256>>>(a16, w16 + 1 * wstride, bq, nullptr, nullptr, qs);
    hmma_main_kernel<2><<<mgrid, 256>>>(a16, w16 + 2 * wstride, bk, nullptr, nullptr, ks);
    hmma_main_kernel<3><<<mgrid, 256>>>(a16, w16 + 3 * wstride, bv, nullptr, nullptr, vt);
    vt_pad_kernel<<<(ZZ * HDIM * 10 + 255) / 256, 256>>>(vt);

    // 5. scores = scale * Qs . Ks^T  (fp32 out)
    hmma_bat_kernel<0><<<dim3(2, 2, ZZ), 256>>>(qs, ks, scores, nullptr,
        SS, SS, KQK, (long)SS * KQK, (long)SS * KQK,
        1, (long)SS * SS, 0, SS, scale);

    // 6. softmax -> split P
    softmax_p_kernel<<<(ZZ * SS + 3) / 4, 128>>>(scores, pp);

    // 7. attn @ V -> split-act a16 (input to Wo)
    hmma_bat_kernel<1><<<dim3(2, 2, ZZ), 256>>>(pp, vt, nullptr, a16,
        SS, HDIM, KPV, (long)SS * KPV, (long)HDIM * KPV,
        HH, 0, 0, 0, 1.0f);

    // 8. Wo + residual -> res
    hmma_main_kernel<0><<<mgrid, 256>>>(a16, w16 + 4 * wstride, bo, emb, res, nullptr);

    // 9. LN2 -> out
    ln_reduce_kernel<<<BB, 256>>>(res, st2);
    ln_apply_kernel<<<(total / 4 + 255) / 256, 256>>>(res, st2, ln2w, ln2b, out);
}

// round 10
// speedup vs baseline: 4.2407x; 1.0640x over previous
#include <cuda_runtime.h>
#include <cuda_bf16.h>
#include <cstdint>
#include <math.h>

// ---------------------------------------------------------------------------
// ViT block, R10 (= R7 candidate; R7/R8/R9 were broker timeouts, never ran).
// bf16x3 HMMA everywhere. 3-stage single-barrier cp.async pipeline in all
// GEMMs; QKV fused into one launch (N=2304) with routed epilogue; split_wt
// fused into one launch.
// ---------------------------------------------------------------------------

#define BB   64
#define SS   196
#define EE   768
#define HH   4
#define HDIM 192
#define PP   16
#define GG   14
#define MM   (BB * SS)        // 12544
#define SE   (SS * EE)        // 150528
#define KP   (3 * EE)         // 2304
#define NKC  (KP / 32)        // 72
#define KQK  (3 * HDIM)       // 576
#define KPV  608              // 588 padded
#define ZZ   (BB * HH)        // 256

// ---------------- scratch ---------------------------------------------------
__device__ float g_emb[MM * EE];
__device__ float g_res[MM * EE];
__device__ float g_scores[(size_t)ZZ * SS * SS];
__device__ float g_stats1[BB * 2];
__device__ float g_stats2[BB * 2];
__device__ float g_bqkv[3 * EE];
__device__ __nv_bfloat16 g_a16[(size_t)MM * KP];
__device__ __nv_bfloat16 g_w16[5][(size_t)EE * KP];
__device__ __nv_bfloat16 g_qs[(size_t)ZZ * SS * KQK];
__device__ __nv_bfloat16 g_ks[(size_t)ZZ * SS * KQK];
__device__ __nv_bfloat16 g_vt[(size_t)ZZ * HDIM * KPV];
__device__ __nv_bfloat16 g_p [(size_t)ZZ * SS * KPV];

// ---------------- helpers ---------------------------------------------------
__device__ __forceinline__ uint32_t smem_u32(const void* p) {
    uint32_t a;
    asm("{ .reg .u64 t; cvta.to.shared.u64 t, %1; cvt.u32.u64 %0, t; }" : "=r"(a) : "l"(p));
    return a;
}
__device__ __forceinline__ void cp16(uint32_t saddr, const void* g) {
    asm volatile("cp.async.cg.shared.global [%0], [%1], 16;"
                 :: "r"(saddr), "l"(__cvta_generic_to_global(g)));
}
#define CP_COMMIT() asm volatile("cp.async.commit_group;" ::: "memory")
#define CP_WAIT1()  asm volatile("cp.async.wait_group 1;" ::: "memory")
#define CP_WAIT0()  asm volatile("cp.async.wait_group 0;" ::: "memory")

__device__ __forceinline__ void ldm_x4(uint32_t* r, uint32_t addr) {
    asm volatile("ldmatrix.sync.aligned.m8n8.x4.shared.b16 {%0,%1,%2,%3}, [%4];"
                 : "=r"(r[0]), "=r"(r[1]), "=r"(r[2]), "=r"(r[3]) : "r"(addr));
}
__device__ __forceinline__ void mma16816(float* c, const uint32_t* a, uint32_t b0, uint32_t b1) {
    asm volatile("mma.sync.aligned.m16n8k16.row.col.f32.bf16.bf16.f32 "
                 "{%0,%1,%2,%3}, {%4,%5,%6,%7}, {%8,%9}, {%0,%1,%2,%3};"
                 : "+f"(c[0]), "+f"(c[1]), "+f"(c[2]), "+f"(c[3])
                 : "r"(a[0]), "r"(a[1]), "r"(a[2]), "r"(a[3]), "r"(b0), "r"(b1));
}
__device__ __forceinline__ uint32_t pack2(float x, float y) {
    __nv_bfloat162 t = __floats2bfloat162_rn(x, y);
    return *(uint32_t*)&t;
}
__device__ __forceinline__ float lopart(float x) {
    return x - __bfloat162float(__float2bfloat16(x));
}

// inner compute (expects sA, sB, acc, lane constants)
#define MMA_TILE_COMPUTE()                                                     \
    _Pragma("unroll")                                                          \
    for (int ks = 0; ks < 2; ks++) {                                           \
        const int k2 = ks * 2;                                                 \
        uint32_t a[4][4], b[2][4];                                             \
        _Pragma("unroll")                                                      \
        for (int mt = 0; mt < 4; mt++) {                                       \
            int row = wm * 64 + mt * 16 + rA;                                  \
            ldm_x4(a[mt], sA + row * 64 + (((k2 + chA) ^ selA) << 4));         \
        }                                                                      \
        _Pragma("unroll")                                                      \
        for (int p = 0; p < 2; p++) {                                          \
            int row = wn * 32 + p * 16 + rB;                                   \
            ldm_x4(b[p], sB + row * 64 + (((k2 + chB) ^ selB) << 4));          \
        }                                                                      \
        _Pragma("unroll")                                                      \
        for (int mt = 0; mt < 4; mt++)                                         \
            _Pragma("unroll")                                                  \
            for (int nt = 0; nt < 4; nt++)                                     \
                mma16816(acc[mt][nt], a[mt],                                   \
                         b[nt >> 1][(nt & 1) * 2], b[nt >> 1][(nt & 1) * 2 + 1]); \
    }

#define LANE_CONSTS()                                                          \
    const int g = lane >> 3, r8 = lane & 7;                                    \
    const int rA = (g & 1) * 8 + r8, selA = (rA >> 1) & 3, chA = g >> 1;       \
    const int rB = (g >> 1) * 8 + r8, selB = (rB >> 1) & 3, chB = g & 1;

// ---------------------------------------------------------------------------
// Main HMMA GEMM: A[MM,KP] x B[N,KP]^T (N = gridDim.y*128), tile 128x128x32.
// 3-stage pipeline, one barrier per K-iter.
// EPI 0: fp32 C (+bias, opt resid).  EPI 4: QKV routed split epilogue.
// ---------------------------------------------------------------------------
template <int EPI>
__global__ void __launch_bounds__(256, 2)
hmma_main_kernel(const __nv_bfloat16* __restrict__ A, const __nv_bfloat16* __restrict__ Bw,
                 const float* __restrict__ bias, const float* __restrict__ resid,
                 float* __restrict__ C,
                 __nv_bfloat16* __restrict__ Oq, __nv_bfloat16* __restrict__ Ok,
                 __nv_bfloat16* __restrict__ Ov)
{
    __shared__ __align__(1024) char smem[49152];   // 3 stages x (A 8KB + B 8KB)
    const uint32_t sb = smem_u32(smem);
    const int tid = threadIdx.x;
    const int lane = tid & 31, wid = tid >> 5;
    const int wm = wid & 1, wn = wid >> 1;
    const int m0 = blockIdx.x * 128, n0 = blockIdx.y * 128;

    const __nv_bfloat16* Abase = A + (long)m0 * KP;
    const __nv_bfloat16* Bbase = Bw + (long)n0 * KP;

#define LOAD_STAGE(s, kc) do {                                                \
        int _ko = (kc) * 32;                                                  \
        uint32_t _base = sb + (s) * 16384;                                    \
        _Pragma("unroll")                                                     \
        for (int _i = 0; _i < 2; _i++) {                                      \
            int _lin = tid + _i * 256;                                        \
            int _row = _lin >> 2, _ch = _lin & 3;                             \
            uint32_t _sw = (uint32_t)(_row * 64 + ((_ch ^ ((_row >> 1) & 3)) << 4)); \
            cp16(_base + _sw,        Abase + (long)_row * KP + _ko + _ch * 8); \
            cp16(_base + 8192 + _sw, Bbase + (long)_row * KP + _ko + _ch * 8); \
        }                                                                     \
    } while (0)

    float acc[4][4][4] = {};
    LANE_CONSTS();

    LOAD_STAGE(0, 0); CP_COMMIT();
    LOAD_STAGE(1, 1); CP_COMMIT();

    int s = 0;
    for (int kc = 0; kc < NKC; kc++) {
        if (kc < NKC - 1) CP_WAIT1(); else CP_WAIT0();
        __syncthreads();
        if (kc + 2 < NKC) {
            int sn = s + 2; if (sn >= 3) sn -= 3;
            LOAD_STAGE(sn, kc + 2); CP_COMMIT();
        }
        const uint32_t sA = sb + s * 16384;
        const uint32_t sB = sA + 8192;
        MMA_TILE_COMPUTE();
        if (++s == 3) s = 0;
    }
#undef LOAD_STAGE

    const int which = n0 / EE;   // CTA-uniform (EPI 4)
#pragma unroll
    for (int mt = 0; mt < 4; mt++) {
#pragma unroll
        for (int half = 0; half < 2; half++) {
            const int gm = m0 + wm * 64 + mt * 16 + (lane >> 2) + half * 8;
#pragma unroll
            for (int nt = 0; nt < 4; nt++) {
                const int gn = n0 + wn * 32 + nt * 8 + (lane & 3) * 2;
                const float c0 = acc[mt][nt][half * 2 + 0];
                const float c1 = acc[mt][nt][half * 2 + 1];
                if (EPI == 0) {
                    float v0 = c0 + bias[gn], v1 = c1 + bias[gn + 1];
                    if (resid) {
                        float2 r = *(const float2*)(resid + (long)gm * EE + gn);
                        v0 += r.x; v1 += r.y;
                    }
                    *(float2*)(C + (long)gm * EE + gn) = make_float2(v0, v1);
                } else {
                    const float y0 = c0 + bias[gn], y1 = c1 + bias[gn + 1];
                    const int gnl = gn - which * EE;
                    const int b = gm / SS, sq = gm - b * SS;
                    const int h = gnl / HDIM, d = gnl - h * HDIM;
                    if (which == 0) {        // Q: [hi | lo | hi]
                        __nv_bfloat16* o = Oq + ((long)(b * HH + h) * SS + sq) * KQK + d;
                        *(uint32_t*)(o)            = pack2(y0, y1);
                        *(uint32_t*)(o + HDIM)     = pack2(lopart(y0), lopart(y1));
                        *(uint32_t*)(o + 2 * HDIM) = pack2(y0, y1);
                    } else if (which == 1) { // K: [hi | hi | lo]
                        __nv_bfloat16* o = Ok + ((long)(b * HH + h) * SS + sq) * KQK + d;
                        *(uint32_t*)(o)            = pack2(y0, y1);
                        *(uint32_t*)(o + HDIM)     = pack2(y0, y1);
                        *(uint32_t*)(o + 2 * HDIM) = pack2(lopart(y0), lopart(y1));
                    } else {                 // Vt transposed: [Vh | Vh | Vl]
                        __nv_bfloat16* o = Ov + ((long)(b * HH + h) * HDIM + d) * KPV + sq;
                        __nv_bfloat16 h0 = __float2bfloat16(y0), h1 = __float2bfloat16(y1);
                        __nv_bfloat16 l0 = __float2bfloat16(lopart(y0)), l1 = __float2bfloat16(lopart(y1));
                        o[0] = h0;  o[SS] = h0;  o[2 * SS] = l0;
                        o += KPV;
                        o[0] = h1;  o[SS] = h1;  o[2 * SS] = l1;
                    }
                }
            }
        }
    }
}

// ---------------------------------------------------------------------------
// Batched HMMA GEMM (NT), 3-stage single-barrier pipeline.
// EPI 0: fp32 C (z-strided). EPI 1: split-act into a16 [hi|lo|hi].
// ---------------------------------------------------------------------------
template <int EPI>
__global__ void __launch_bounds__(256, 2)
hmma_bat_kernel(const __nv_bfloat16* __restrict__ Ag, const __nv_bfloat16* __restrict__ Bg,
                float* __restrict__ C, __nv_bfloat16* __restrict__ O16,
                int Md, int Nd, int Kd, long sA_, long sB_,
                int Hdiv, long sC1, long sC2, int ldc, float scale)
{
    __shared__ __align__(1024) char smem[49152];
    const uint32_t sb = smem_u32(smem);
    const int tid = threadIdx.x;
    const int lane = tid & 31, wid = tid >> 5;
    const int wm = wid & 1, wn = wid >> 1;
    const int m0 = blockIdx.x * 128, n0 = blockIdx.y * 128;
    const int z = blockIdx.z;
    const int z1 = z / Hdiv, z2 = z - z1 * Hdiv;

    const __nv_bfloat16* Abase = Ag + (long)z * sA_;
    const __nv_bfloat16* Bbase = Bg + (long)z * sB_;
    const int nkc = Kd >> 5;

#define LOAD_STAGE_B(s, kc) do {                                              \
        int _ko = (kc) * 32;                                                  \
        uint32_t _base = sb + (s) * 16384;                                    \
        _Pragma("unroll")                                                     \
        for (int _i = 0; _i < 2; _i++) {                                      \
            int _lin = tid + _i * 256;                                        \
            int _row = _lin >> 2, _ch = _lin & 3;                             \
            uint32_t _sw = (uint32_t)(_row * 64 + ((_ch ^ ((_row >> 1) & 3)) << 4)); \
            int _ra = min(m0 + _row, Md - 1);                                 \
            int _rb = min(n0 + _row, Nd - 1);                                 \
            cp16(_base + _sw,        Abase + (long)_ra * Kd + _ko + _ch * 8); \
            cp16(_base + 8192 + _sw, Bbase + (long)_rb * Kd + _ko + _ch * 8); \
        }                                                                     \
    } while (0)

    float acc[4][4][4] = {};
    LANE_CONSTS();

    LOAD_STAGE_B(0, 0); CP_COMMIT();
    LOAD_STAGE_B(1, 1); CP_COMMIT();

    int s = 0;
    for (int kc = 0; kc < nkc; kc++) {
        if (kc < nkc - 1) CP_WAIT1(); else CP_WAIT0();
        __syncthreads();
        if (kc + 2 < nkc) {
            int sn = s + 2; if (sn >= 3) sn -= 3;
            LOAD_STAGE_B(sn, kc + 2); CP_COMMIT();
        }
        const uint32_t sA = sb + s * 16384;
        const uint32_t sB = sA + 8192;
        MMA_TILE_COMPUTE();
        if (++s == 3) s = 0;
    }
#undef LOAD_STAGE_B

    float* Cz = (EPI == 0) ? (C + (long)z1 * sC1 + (long)z2 * sC2) : nullptr;
#pragma unroll
    for (int mt = 0; mt < 4; mt++) {
#pragma unroll
        for (int half = 0; half < 2; half++) {
            const int gm = m0 + wm * 64 + mt * 16 + (lane >> 2) + half * 8;
            if (gm >= Md) continue;
#pragma unroll
            for (int nt = 0; nt < 4; nt++) {
                const int gn = n0 + wn * 32 + nt * 8 + (lane & 3) * 2;
                if (gn >= Nd) continue;
                const float c0 = acc[mt][nt][half * 2 + 0] * scale;
                const float c1 = acc[mt][nt][half * 2 + 1] * scale;
                if (EPI == 0) {
                    *(float2*)(Cz + (long)gm * ldc + gn) = make_float2(c0, c1);
                } else {
                    const long row = (long)z1 * SS + gm;
                    const int  col = z2 * HDIM + gn;
                    __nv_bfloat16* o = O16 + row * KP + col;
                    *(uint32_t*)(o)          = pack2(c0, c1);
                    *(uint32_t*)(o + EE)     = pack2(lopart(c0), lopart(c1));
                    *(uint32_t*)(o + 2 * EE) = pack2(c0, c1);
                }
            }
        }
    }
}

// ---------------------------------------------------------------------------
// splits / im2col / LN / softmax
// ---------------------------------------------------------------------------
__device__ __forceinline__ void split1(float x, __nv_bfloat16& h, __nv_bfloat16& l) {
    h = __float2bfloat16(x);
    l = __float2bfloat16(x - __bfloat162float(h));
}

// all 5 weights in one launch; weight layout [hi | hi | lo]
__global__ void split_wt5_kernel(const float* __restrict__ w0, const float* __restrict__ w1,
                                 const float* __restrict__ w2, const float* __restrict__ w3,
                                 const float* __restrict__ w4, __nv_bfloat16* __restrict__ out) {
    const int per = EE * EE / 4;
    int idx = blockIdx.x * blockDim.x + threadIdx.x;
    if (idx >= 5 * per) return;
    int wsel = idx / per, r = idx - wsel * per;
    const float* w = (wsel == 0) ? w0 : (wsel == 1) ? w1 : (wsel == 2) ? w2 : (wsel == 3) ? w3 : w4;
    int n = r / (EE / 4), k4 = (r % (EE / 4)) * 4;
    float4 v = ((const float4*)w)[r];
    __nv_bfloat16 h[4], l[4];
    split1(v.x, h[0], l[0]); split1(v.y, h[1], l[1]);
    split1(v.z, h[2], l[2]); split1(v.w, h[3], l[3]);
    __nv_bfloat16* o = out + (size_t)wsel * EE * KP + (long)n * KP;
    *(uint2*)(o + k4)          = *(uint2*)h;
    *(uint2*)(o + EE + k4)     = *(uint2*)h;
    *(uint2*)(o + 2 * EE + k4) = *(uint2*)l;
}

__global__ void im2col_split_kernel(const float* __restrict__ x, __nv_bfloat16* __restrict__ out) {
    int idx = blockIdx.x * blockDim.x + threadIdx.x;
    if (idx >= MM * EE / 2) return;
    int e2 = idx % (EE / 2);
    int s  = (idx / (EE / 2)) % SS;
    int b  = idx / ((EE / 2) * SS);
    int e  = e2 * 2;
    int c = e >> 8, r = e & 255, py = r >> 4, px = r & 15;
    int gy = s / GG, gx = s % GG;
    const float* xp = x + (((long)(b * 3 + c) * 224) + gy * PP + py) * 224 + gx * PP + px;
    float2 v = *(const float2*)xp;
    __nv_bfloat16 h[2], l[2];
    split1(v.x, h[0], l[0]); split1(v.y, h[1], l[1]);
    __nv_bfloat16* o = out + (long)(b * SS + s) * KP;
    *(uint32_t*)(o + e)          = *(uint32_t*)h;
    *(uint32_t*)(o + EE + e)     = *(uint32_t*)l;
    *(uint32_t*)(o + 2 * EE + e) = *(uint32_t*)h;
}

__global__ void ln_reduce_kernel(const float* __restrict__ in, float* __restrict__ stats) {
    int b = blockIdx.x;
    const float4* p = (const float4*)(in + (long)b * SE);
    float s = 0.f, s2 = 0.f;
    for (int i = threadIdx.x; i < SE / 4; i += blockDim.x) {
        float4 v = p[i];
        s  += v.x + v.y + v.z + v.w;
        s2 += v.x * v.x + v.y * v.y + v.z * v.z + v.w * v.w;
    }
    __shared__ float sh[256], sh2[256];
    sh[threadIdx.x] = s; sh2[threadIdx.x] = s2;
    __syncthreads();
    for (int st = 128; st > 0; st >>= 1) {
        if (threadIdx.x < st) {
            sh[threadIdx.x]  += sh[threadIdx.x + st];
            sh2[threadIdx.x] += sh2[threadIdx.x + st];
        }
        __syncthreads();
    }
    if (threadIdx.x == 0) {
        float mu  = sh[0] / (float)SE;
        float var = sh2[0] / (float)SE - mu * mu;
        stats[b * 2 + 0] = mu;
        stats[b * 2 + 1] = rsqrtf(var + 1e-5f);
    }
}

__global__ void ln_apply_kernel(const float* __restrict__ in, const float* __restrict__ stats,
                                const float* __restrict__ w, const float* __restrict__ bw,
                                float* __restrict__ out) {
    int i4 = blockIdx.x * blockDim.x + threadIdx.x;
    if (i4 >= (MM * EE) / 4) return;
    int b = i4 / (SE / 4), se4 = i4 - b * (SE / 4);
    float mu = stats[b * 2 + 0], rs = stats[b * 2 + 1];
    float4 v  = ((const float4*)in)[i4];
    float4 wv = ((const float4*)w)[se4];
    float4 bv = ((const float4*)bw)[se4];
    float4 o;
    o.x = (v.x - mu) * rs * wv.x + bv.x;
    o.y = (v.y - mu) * rs * wv.y + bv.y;
    o.z = (v.z - mu) * rs * wv.z + bv.z;
    o.w = (v.w - mu) * rs * wv.w + bv.w;
    ((float4*)out)[i4] = o;
}

__global__ void ln_apply_split_kernel(const float* __restrict__ in, const float* __restrict__ stats,
                                      const float* __restrict__ w, const float* __restrict__ bw,
                                      __nv_bfloat16* __restrict__ out) {
    int i4 = blockIdx.x * blockDim.x + threadIdx.x;
    if (i4 >= (MM * EE) / 4) return;
    int b = i4 / (SE / 4), se4 = i4 - b * (SE / 4);
    int m = i4 / (EE / 4), k4 = (i4 % (EE / 4)) * 4;
    float mu = stats[b * 2 + 0], rs = stats[b * 2 + 1];
    float4 v  = ((const float4*)in)[i4];
    float4 wv = ((const float4*)w)[se4];
    float4 bv = ((const float4*)bw)[se4];
    float y[4];
    y[0] = (v.x - mu) * rs * wv.x + bv.x;
    y[1] = (v.y - mu) * rs * wv.y + bv.y;
    y[2] = (v.z - mu) * rs * wv.z + bv.z;
    y[3] = (v.w - mu) * rs * wv.w + bv.w;
    __nv_bfloat16 h[4], l[4];
    split1(y[0], h[0], l[0]); split1(y[1], h[1], l[1]);
    split1(y[2], h[2], l[2]); split1(y[3], h[3], l[3]);
    __nv_bfloat16* o = out + (long)m * KP;
    *(uint2*)(o + k4)          = *(uint2*)h;
    *(uint2*)(o + EE + k4)     = *(uint2*)l;
    *(uint2*)(o + 2 * EE + k4) = *(uint2*)h;
}

// softmax over 196 cols; emits split-bf16 P [Ph | Pl | Ph] + zero pad.
__global__ void softmax_p_kernel(const float* __restrict__ sc, __nv_bfloat16* __restrict__ P) {
    int warp = threadIdx.x >> 5, lane = threadIdx.x & 31;
    long row = (long)blockIdx.x * 4 + warp;
    if (row >= (long)ZZ * SS) return;
    const float* p = sc + row * SS;
    float v[7];
    float mx = -1e30f;
#pragma unroll
    for (int i = 0; i < 7; i++) {
        int idx = lane + i * 32;
        v[i] = (idx < SS) ? p[idx] : -1e30f;
        mx = fmaxf(mx, v[i]);
    }
#pragma unroll
    for (int o = 16; o > 0; o >>= 1) mx = fmaxf(mx, __shfl_xor_sync(0xFFFFFFFFu, mx, o));
    float sum = 0.f;
#pragma unroll
    for (int i = 0; i < 7; i++) { v[i] = expf(v[i] - mx); sum += v[i]; }
#pragma unroll
    for (int o = 16; o > 0; o >>= 1) sum += __shfl_xor_sync(0xFFFFFFFFu, sum, o);
    float inv = 1.0f / sum;
    __nv_bfloat16* o = P + row * KPV;
#pragma unroll
    for (int i = 0; i < 7; i++) {
        int idx = lane + i * 32;
        if (idx < SS) {
            float y = v[i] * inv;
            __nv_bfloat16 h, l;
            split1(y, h, l);
            o[idx] = h; o[SS + idx] = l; o[2 * SS + idx] = h;
        }
    }
    if (lane < 20) o[3 * SS + lane] = __float2bfloat16(0.f);
}

// zero pad columns (588..607) of Vt rows
__global__ void vt_pad_kernel(__nv_bfloat16* __restrict__ Vt) {
    int idx = blockIdx.x * blockDim.x + threadIdx.x;
    if (idx >= ZZ * HDIM * 10) return;
    int r = idx / 10, c = idx % 10;
    *(uint32_t*)(Vt + (long)r * KPV + 588 + c * 2) = 0u;
}

// ---------------------------------------------------------------------------
extern "C" void kernel_launch(void* const* d_in, const int* in_sizes, int n_in,
                              void* d_out, int out_size) {
    const float* x      = (const float*)d_in[0];
    const float* conv_w = (const float*)d_in[1];
    const float* conv_b = (const float*)d_in[2];
    const float* wq = (const float*)d_in[3];
    const float* bq = (const float*)d_in[4];
    const float* wk = (const float*)d_in[5];
    const float* bk = (const float*)d_in[6];
    const float* wv = (const float*)d_in[7];
    const float* bv = (const float*)d_in[8];
    const float* wo = (const float*)d_in[9];
    const float* bo = (const float*)d_in[10];
    const float* ln1w = (const float*)d_in[11];
    const float* ln1b = (const float*)d_in[12];
    const float* ln2w = (const float*)d_in[13];
    const float* ln2b = (const float*)d_in[14];
    float* out = (float*)d_out;

    float *emb, *res, *scores, *st1, *st2, *bqkv;
    __nv_bfloat16 *a16, *w16, *qs, *ks, *vt, *pp;
    cudaGetSymbolAddress((void**)&emb,    g_emb);
    cudaGetSymbolAddress((void**)&res,    g_res);
    cudaGetSymbolAddress((void**)&scores, g_scores);
    cudaGetSymbolAddress((void**)&st1,    g_stats1);
    cudaGetSymbolAddress((void**)&st2,    g_stats2);
    cudaGetSymbolAddress((void**)&bqkv,   g_bqkv);
    cudaGetSymbolAddress((void**)&a16,    g_a16);
    cudaGetSymbolAddress((void**)&w16,    g_w16);
    cudaGetSymbolAddress((void**)&qs,     g_qs);
    cudaGetSymbolAddress((void**)&ks,     g_ks);
    cudaGetSymbolAddress((void**)&vt,     g_vt);
    cudaGetSymbolAddress((void**)&pp,     g_p);

    const int total = MM * EE;
    const size_t wstride = (size_t)EE * KP;
    const float scale = 1.0f / sqrtf((float)HDIM);

    // bias concat for QKV (D2D async copies are graph-capturable)
    cudaMemcpyAsync(bqkv,          bq, EE * sizeof(float), cudaMemcpyDeviceToDevice);
    cudaMemcpyAsync(bqkv + EE,     bk, EE * sizeof(float), cudaMemcpyDeviceToDevice);
    cudaMemcpyAsync(bqkv + 2 * EE, bv, EE * sizeof(float), cudaMemcpyDeviceToDevice);

    // 0. split all 5 weights in one launch
    const int wtot = 5 * EE * EE / 4;
    split_wt5_kernel<<<(wtot + 255) / 256, 256>>>(conv_w, wq, wk, wv, wo, w16);

    // 1. im2col + split
    im2col_split_kernel<<<(total / 2 + 255) / 256, 256>>>(x, a16);

    // 2. patch embed -> emb (fp32)
    hmma_main_kernel<0><<<dim3(MM / 128, 6), 256>>>(a16, w16, conv_b, nullptr, emb,
                                                    nullptr, nullptr, nullptr);

    // 3. LN1 -> split a16
    ln_reduce_kernel<<<BB, 256>>>(emb, st1);
    ln_apply_split_kernel<<<(total / 4 + 255) / 256, 256>>>(emb, st1, ln1w, ln1b, a16);

    // 4. QKV in ONE launch -> split per-head layouts
    hmma_main_kernel<4><<<dim3(MM / 128, 18), 256>>>(a16, w16 + 1 * wstride, bqkv, nullptr,
                                                     nullptr, qs, ks, vt);
    vt_pad_kernel<<<(ZZ * HDIM * 10 + 255) / 256, 256>>>(vt);

    // 5. scores = scale * Qs . Ks^T
    hmma_bat_kernel<0><<<dim3(2, 2, ZZ), 256>>>(qs, ks, scores, nullptr,
        SS, SS, KQK, (long)SS * KQK, (long)SS * KQK,
        1, (long)SS * SS, 0, SS, scale);

    // 6. softmax -> split P
    softmax_p_kernel<<<(ZZ * SS + 3) / 4, 128>>>(scores, pp);

    // 7. attn @ V -> split-act a16
    hmma_bat_kernel<1><<<dim3(2, 2, ZZ), 256>>>(pp, vt, nullptr, a16,
        SS, HDIM, KPV, (long)SS * KPV, (long)HDIM * KPV,
        HH, 0, 0, 0, 1.0f);

    // 8. Wo + residual -> res
    hmma_main_kernel<0><<<dim3(MM / 128, 6), 256>>>(a16, w16 + 4 * wstride, bo, emb, res,
                                                    nullptr, nullptr, nullptr);

    // 9. LN2 -> out
    ln_reduce_kernel<<<BB, 256>>>(res, st2);
    ln_apply_kernel<<<(total / 4 + 255) / 256, 256>>>(res, st2, ln2w, ln2b, out);
}

// round 11
// speedup vs baseline: 4.4042x; 1.0386x over previous
#include <cuda_runtime.h>
#include <cuda_bf16.h>
#include <cstdint>
#include <math.h>

// ---------------------------------------------------------------------------
// ViT block, R11: R10 + parallelized LayerNorm reduction (8 partials/image,
// 512 CTAs, deterministic) + tiny finalize kernel. Everything else unchanged.
// ---------------------------------------------------------------------------

#define BB   64
#define SS   196
#define EE   768
#define HH   4
#define HDIM 192
#define PP   16
#define GG   14
#define MM   (BB * SS)        // 12544
#define SE   (SS * EE)        // 150528
#define KP   (3 * EE)         // 2304
#define NKC  (KP / 32)        // 72
#define KQK  (3 * HDIM)       // 576
#define KPV  608              // 588 padded
#define ZZ   (BB * HH)        // 256
#define LNSEG 8               // partials per image

// ---------------- scratch ---------------------------------------------------
__device__ float g_emb[MM * EE];
__device__ float g_res[MM * EE];
__device__ float g_scores[(size_t)ZZ * SS * SS];
__device__ float2 g_part[BB * LNSEG];
__device__ float g_stats1[BB * 2];
__device__ float g_stats2[BB * 2];
__device__ float g_bqkv[3 * EE];
__device__ __nv_bfloat16 g_a16[(size_t)MM * KP];
__device__ __nv_bfloat16 g_w16[5][(size_t)EE * KP];
__device__ __nv_bfloat16 g_qs[(size_t)ZZ * SS * KQK];
__device__ __nv_bfloat16 g_ks[(size_t)ZZ * SS * KQK];
__device__ __nv_bfloat16 g_vt[(size_t)ZZ * HDIM * KPV];
__device__ __nv_bfloat16 g_p [(size_t)ZZ * SS * KPV];

// ---------------- helpers ---------------------------------------------------
__device__ __forceinline__ uint32_t smem_u32(const void* p) {
    uint32_t a;
    asm("{ .reg .u64 t; cvta.to.shared.u64 t, %1; cvt.u32.u64 %0, t; }" : "=r"(a) : "l"(p));
    return a;
}
__device__ __forceinline__ void cp16(uint32_t saddr, const void* g) {
    asm volatile("cp.async.cg.shared.global [%0], [%1], 16;"
                 :: "r"(saddr), "l"(__cvta_generic_to_global(g)));
}
#define CP_COMMIT() asm volatile("cp.async.commit_group;" ::: "memory")
#define CP_WAIT1()  asm volatile("cp.async.wait_group 1;" ::: "memory")
#define CP_WAIT0()  asm volatile("cp.async.wait_group 0;" ::: "memory")

__device__ __forceinline__ void ldm_x4(uint32_t* r, uint32_t addr) {
    asm volatile("ldmatrix.sync.aligned.m8n8.x4.shared.b16 {%0,%1,%2,%3}, [%4];"
                 : "=r"(r[0]), "=r"(r[1]), "=r"(r[2]), "=r"(r[3]) : "r"(addr));
}
__device__ __forceinline__ void mma16816(float* c, const uint32_t* a, uint32_t b0, uint32_t b1) {
    asm volatile("mma.sync.aligned.m16n8k16.row.col.f32.bf16.bf16.f32 "
                 "{%0,%1,%2,%3}, {%4,%5,%6,%7}, {%8,%9}, {%0,%1,%2,%3};"
                 : "+f"(c[0]), "+f"(c[1]), "+f"(c[2]), "+f"(c[3])
                 : "r"(a[0]), "r"(a[1]), "r"(a[2]), "r"(a[3]), "r"(b0), "r"(b1));
}
__device__ __forceinline__ uint32_t pack2(float x, float y) {
    __nv_bfloat162 t = __floats2bfloat162_rn(x, y);
    return *(uint32_t*)&t;
}
__device__ __forceinline__ float lopart(float x) {
    return x - __bfloat162float(__float2bfloat16(x));
}

// inner compute (expects sA, sB, acc, lane constants)
#define MMA_TILE_COMPUTE()                                                     \
    _Pragma("unroll")                                                          \
    for (int ks = 0; ks < 2; ks++) {                                           \
        const int k2 = ks * 2;                                                 \
        uint32_t a[4][4], b[2][4];                                             \
        _Pragma("unroll")                                                      \
        for (int mt = 0; mt < 4; mt++) {                                       \
            int row = wm * 64 + mt * 16 + rA;                                  \
            ldm_x4(a[mt], sA + row * 64 + (((k2 + chA) ^ selA) << 4));         \
        }                                                                      \
        _Pragma("unroll")                                                      \
        for (int p = 0; p < 2; p++) {                                          \
            int row = wn * 32 + p * 16 + rB;                                   \
            ldm_x4(b[p], sB + row * 64 + (((k2 + chB) ^ selB) << 4));          \
        }                                                                      \
        _Pragma("unroll")                                                      \
        for (int mt = 0; mt < 4; mt++)                                         \
            _Pragma("unroll")                                                  \
            for (int nt = 0; nt < 4; nt++)                                     \
                mma16816(acc[mt][nt], a[mt],                                   \
                         b[nt >> 1][(nt & 1) * 2], b[nt >> 1][(nt & 1) * 2 + 1]); \
    }

#define LANE_CONSTS()                                                          \
    const int g = lane >> 3, r8 = lane & 7;                                    \
    const int rA = (g & 1) * 8 + r8, selA = (rA >> 1) & 3, chA = g >> 1;       \
    const int rB = (g >> 1) * 8 + r8, selB = (rB >> 1) & 3, chB = g & 1;

// ---------------------------------------------------------------------------
// Main HMMA GEMM: A[MM,KP] x B[N,KP]^T (N = gridDim.y*128), tile 128x128x32.
// 3-stage pipeline, one barrier per K-iter.
// EPI 0: fp32 C (+bias, opt resid).  EPI 4: QKV routed split epilogue.
// ---------------------------------------------------------------------------
template <int EPI>
__global__ void __launch_bounds__(256, 2)
hmma_main_kernel(const __nv_bfloat16* __restrict__ A, const __nv_bfloat16* __restrict__ Bw,
                 const float* __restrict__ bias, const float* __restrict__ resid,
                 float* __restrict__ C,
                 __nv_bfloat16* __restrict__ Oq, __nv_bfloat16* __restrict__ Ok,
                 __nv_bfloat16* __restrict__ Ov)
{
    __shared__ __align__(1024) char smem[49152];   // 3 stages x (A 8KB + B 8KB)
    const uint32_t sb = smem_u32(smem);
    const int tid = threadIdx.x;
    const int lane = tid & 31, wid = tid >> 5;
    const int wm = wid & 1, wn = wid >> 1;
    const int m0 = blockIdx.x * 128, n0 = blockIdx.y * 128;

    const __nv_bfloat16* Abase = A + (long)m0 * KP;
    const __nv_bfloat16* Bbase = Bw + (long)n0 * KP;

#define LOAD_STAGE(s, kc) do {                                                \
        int _ko = (kc) * 32;                                                  \
        uint32_t _base = sb + (s) * 16384;                                    \
        _Pragma("unroll")                                                     \
        for (int _i = 0; _i < 2; _i++) {                                      \
            int _lin = tid + _i * 256;                                        \
            int _row = _lin >> 2, _ch = _lin & 3;                             \
            uint32_t _sw = (uint32_t)(_row * 64 + ((_ch ^ ((_row >> 1) & 3)) << 4)); \
            cp16(_base + _sw,        Abase + (long)_row * KP + _ko + _ch * 8); \
            cp16(_base + 8192 + _sw, Bbase + (long)_row * KP + _ko + _ch * 8); \
        }                                                                     \
    } while (0)

    float acc[4][4][4] = {};
    LANE_CONSTS();

    LOAD_STAGE(0, 0); CP_COMMIT();
    LOAD_STAGE(1, 1); CP_COMMIT();

    int s = 0;
    for (int kc = 0; kc < NKC; kc++) {
        if (kc < NKC - 1) CP_WAIT1(); else CP_WAIT0();
        __syncthreads();
        if (kc + 2 < NKC) {
            int sn = s + 2; if (sn >= 3) sn -= 3;
            LOAD_STAGE(sn, kc + 2); CP_COMMIT();
        }
        const uint32_t sA = sb + s * 16384;
        const uint32_t sB = sA + 8192;
        MMA_TILE_COMPUTE();
        if (++s == 3) s = 0;
    }
#undef LOAD_STAGE

    const int which = n0 / EE;   // CTA-uniform (EPI 4)
#pragma unroll
    for (int mt = 0; mt < 4; mt++) {
#pragma unroll
        for (int half = 0; half < 2; half++) {
            const int gm = m0 + wm * 64 + mt * 16 + (lane >> 2) + half * 8;
#pragma unroll
            for (int nt = 0; nt < 4; nt++) {
                const int gn = n0 + wn * 32 + nt * 8 + (lane & 3) * 2;
                const float c0 = acc[mt][nt][half * 2 + 0];
                const float c1 = acc[mt][nt][half * 2 + 1];
                if (EPI == 0) {
                    float v0 = c0 + bias[gn], v1 = c1 + bias[gn + 1];
                    if (resid) {
                        float2 r = *(const float2*)(resid + (long)gm * EE + gn);
                        v0 += r.x; v1 += r.y;
                    }
                    *(float2*)(C + (long)gm * EE + gn) = make_float2(v0, v1);
                } else {
                    const float y0 = c0 + bias[gn], y1 = c1 + bias[gn + 1];
                    const int gnl = gn - which * EE;
                    const int b = gm / SS, sq = gm - b * SS;
                    const int h = gnl / HDIM, d = gnl - h * HDIM;
                    if (which == 0) {        // Q: [hi | lo | hi]
                        __nv_bfloat16* o = Oq + ((long)(b * HH + h) * SS + sq) * KQK + d;
                        *(uint32_t*)(o)            = pack2(y0, y1);
                        *(uint32_t*)(o + HDIM)     = pack2(lopart(y0), lopart(y1));
                        *(uint32_t*)(o + 2 * HDIM) = pack2(y0, y1);
                    } else if (which == 1) { // K: [hi | hi | lo]
                        __nv_bfloat16* o = Ok + ((long)(b * HH + h) * SS + sq) * KQK + d;
                        *(uint32_t*)(o)            = pack2(y0, y1);
                        *(uint32_t*)(o + HDIM)     = pack2(y0, y1);
                        *(uint32_t*)(o + 2 * HDIM) = pack2(lopart(y0), lopart(y1));
                    } else {                 // Vt transposed: [Vh | Vh | Vl]
                        __nv_bfloat16* o = Ov + ((long)(b * HH + h) * HDIM + d) * KPV + sq;
                        __nv_bfloat16 h0 = __float2bfloat16(y0), h1 = __float2bfloat16(y1);
                        __nv_bfloat16 l0 = __float2bfloat16(lopart(y0)), l1 = __float2bfloat16(lopart(y1));
                        o[0] = h0;  o[SS] = h0;  o[2 * SS] = l0;
                        o += KPV;
                        o[0] = h1;  o[SS] = h1;  o[2 * SS] = l1;
                    }
                }
            }
        }
    }
}

// ---------------------------------------------------------------------------
// Batched HMMA GEMM (NT), 3-stage single-barrier pipeline.
// EPI 0: fp32 C (z-strided). EPI 1: split-act into a16 [hi|lo|hi].
// ---------------------------------------------------------------------------
template <int EPI>
__global__ void __launch_bounds__(256, 2)
hmma_bat_kernel(const __nv_bfloat16* __restrict__ Ag, const __nv_bfloat16* __restrict__ Bg,
                float* __restrict__ C, __nv_bfloat16* __restrict__ O16,
                int Md, int Nd, int Kd, long sA_, long sB_,
                int Hdiv, long sC1, long sC2, int ldc, float scale)
{
    __shared__ __align__(1024) char smem[49152];
    const uint32_t sb = smem_u32(smem);
    const int tid = threadIdx.x;
    const int lane = tid & 31, wid = tid >> 5;
    const int wm = wid & 1, wn = wid >> 1;
    const int m0 = blockIdx.x * 128, n0 = blockIdx.y * 128;
    const int z = blockIdx.z;
    const int z1 = z / Hdiv, z2 = z - z1 * Hdiv;

    const __nv_bfloat16* Abase = Ag + (long)z * sA_;
    const __nv_bfloat16* Bbase = Bg + (long)z * sB_;
    const int nkc = Kd >> 5;

#define LOAD_STAGE_B(s, kc) do {                                              \
        int _ko = (kc) * 32;                                                  \
        uint32_t _base = sb + (s) * 16384;                                    \
        _Pragma("unroll")                                                     \
        for (int _i = 0; _i < 2; _i++) {                                      \
            int _lin = tid + _i * 256;                                        \
            int _row = _lin >> 2, _ch = _lin & 3;                             \
            uint32_t _sw = (uint32_t)(_row * 64 + ((_ch ^ ((_row >> 1) & 3)) << 4)); \
            int _ra = min(m0 + _row, Md - 1);                                 \
            int _rb = min(n0 + _row, Nd - 1);                                 \
            cp16(_base + _sw,        Abase + (long)_ra * Kd + _ko + _ch * 8); \
            cp16(_base + 8192 + _sw, Bbase + (long)_rb * Kd + _ko + _ch * 8); \
        }                                                                     \
    } while (0)

    float acc[4][4][4] = {};
    LANE_CONSTS();

    LOAD_STAGE_B(0, 0); CP_COMMIT();
    LOAD_STAGE_B(1, 1); CP_COMMIT();

    int s = 0;
    for (int kc = 0; kc < nkc; kc++) {
        if (kc < nkc - 1) CP_WAIT1(); else CP_WAIT0();
        __syncthreads();
        if (kc + 2 < nkc) {
            int sn = s + 2; if (sn >= 3) sn -= 3;
            LOAD_STAGE_B(sn, kc + 2); CP_COMMIT();
        }
        const uint32_t sA = sb + s * 16384;
        const uint32_t sB = sA + 8192;
        MMA_TILE_COMPUTE();
        if (++s == 3) s = 0;
    }
#undef LOAD_STAGE_B

    float* Cz = (EPI == 0) ? (C + (long)z1 * sC1 + (long)z2 * sC2) : nullptr;
#pragma unroll
    for (int mt = 0; mt < 4; mt++) {
#pragma unroll
        for (int half = 0; half < 2; half++) {
            const int gm = m0 + wm * 64 + mt * 16 + (lane >> 2) + half * 8;
            if (gm >= Md) continue;
#pragma unroll
            for (int nt = 0; nt < 4; nt++) {
                const int gn = n0 + wn * 32 + nt * 8 + (lane & 3) * 2;
                if (gn >= Nd) continue;
                const float c0 = acc[mt][nt][half * 2 + 0] * scale;
                const float c1 = acc[mt][nt][half * 2 + 1] * scale;
                if (EPI == 0) {
                    *(float2*)(Cz + (long)gm * ldc + gn) = make_float2(c0, c1);
                } else {
                    const long row = (long)z1 * SS + gm;
                    const int  col = z2 * HDIM + gn;
                    __nv_bfloat16* o = O16 + row * KP + col;
                    *(uint32_t*)(o)          = pack2(c0, c1);
                    *(uint32_t*)(o + EE)     = pack2(lopart(c0), lopart(c1));
                    *(uint32_t*)(o + 2 * EE) = pack2(c0, c1);
                }
            }
        }
    }
}

// ---------------------------------------------------------------------------
// splits / im2col / LN / softmax
// ---------------------------------------------------------------------------
__device__ __forceinline__ void split1(float x, __nv_bfloat16& h, __nv_bfloat16& l) {
    h = __float2bfloat16(x);
    l = __float2bfloat16(x - __bfloat162float(h));
}

// all 5 weights in one launch; weight layout [hi | hi | lo]
__global__ void split_wt5_kernel(const float* __restrict__ w0, const float* __restrict__ w1,
                                 const float* __restrict__ w2, const float* __restrict__ w3,
                                 const float* __restrict__ w4, __nv_bfloat16* __restrict__ out) {
    const int per = EE * EE / 4;
    int idx = blockIdx.x * blockDim.x + threadIdx.x;
    if (idx >= 5 * per) return;
    int wsel = idx / per, r = idx - wsel * per;
    const float* w = (wsel == 0) ? w0 : (wsel == 1) ? w1 : (wsel == 2) ? w2 : (wsel == 3) ? w3 : w4;
    int n = r / (EE / 4), k4 = (r % (EE / 4)) * 4;
    float4 v = ((const float4*)w)[r];
    __nv_bfloat16 h[4], l[4];
    split1(v.x, h[0], l[0]); split1(v.y, h[1], l[1]);
    split1(v.z, h[2], l[2]); split1(v.w, h[3], l[3]);
    __nv_bfloat16* o = out + (size_t)wsel * EE * KP + (long)n * KP;
    *(uint2*)(o + k4)          = *(uint2*)h;
    *(uint2*)(o + EE + k4)     = *(uint2*)h;
    *(uint2*)(o + 2 * EE + k4) = *(uint2*)l;
}

__global__ void im2col_split_kernel(const float* __restrict__ x, __nv_bfloat16* __restrict__ out) {
    int idx = blockIdx.x * blockDim.x + threadIdx.x;
    if (idx >= MM * EE / 2) return;
    int e2 = idx % (EE / 2);
    int s  = (idx / (EE / 2)) % SS;
    int b  = idx / ((EE / 2) * SS);
    int e  = e2 * 2;
    int c = e >> 8, r = e & 255, py = r >> 4, px = r & 15;
    int gy = s / GG, gx = s % GG;
    const float* xp = x + (((long)(b * 3 + c) * 224) + gy * PP + py) * 224 + gx * PP + px;
    float2 v = *(const float2*)xp;
    __nv_bfloat16 h[2], l[2];
    split1(v.x, h[0], l[0]); split1(v.y, h[1], l[1]);
    __nv_bfloat16* o = out + (long)(b * SS + s) * KP;
    *(uint32_t*)(o + e)          = *(uint32_t*)h;
    *(uint32_t*)(o + EE + e)     = *(uint32_t*)l;
    *(uint32_t*)(o + 2 * EE + e) = *(uint32_t*)h;
}

// LN partial reduce: 8 segments per image, 512 CTAs total. Deterministic.
__global__ void ln_reduce_part_kernel(const float* __restrict__ in, float2* __restrict__ part) {
    const int blk = blockIdx.x;          // 0..BB*LNSEG-1
    const int b = blk >> 3, seg = blk & (LNSEG - 1);
    const int n4 = SE / 4 / LNSEG;       // 4704 float4 per segment
    const float4* p = (const float4*)(in + (long)b * SE) + seg * n4;
    float s = 0.f, s2 = 0.f;
    for (int i = threadIdx.x; i < n4; i += 256) {
        float4 v = p[i];
        s  += v.x + v.y + v.z + v.w;
        s2 += v.x * v.x + v.y * v.y + v.z * v.z + v.w * v.w;
    }
    __shared__ float sh[256], sh2[256];
    sh[threadIdx.x] = s; sh2[threadIdx.x] = s2;
    __syncthreads();
    for (int st = 128; st > 0; st >>= 1) {
        if (threadIdx.x < st) {
            sh[threadIdx.x]  += sh[threadIdx.x + st];
            sh2[threadIdx.x] += sh2[threadIdx.x + st];
        }
        __syncthreads();
    }
    if (threadIdx.x == 0) part[blk] = make_float2(sh[0], sh2[0]);
}

// fold partials -> stats[b] = {mu, rsqrt}
__global__ void ln_finalize_kernel(const float2* __restrict__ part, float* __restrict__ stats) {
    int b = threadIdx.x;
    if (b >= BB) return;
    float s = 0.f, s2 = 0.f;
#pragma unroll
    for (int i = 0; i < LNSEG; i++) {
        float2 v = part[b * LNSEG + i];
        s += v.x; s2 += v.y;
    }
    float mu  = s / (float)SE;
    float var = s2 / (float)SE - mu * mu;
    stats[b * 2 + 0] = mu;
    stats[b * 2 + 1] = rsqrtf(var + 1e-5f);
}

__global__ void ln_apply_kernel(const float* __restrict__ in, const float* __restrict__ stats,
                                const float* __restrict__ w, const float* __restrict__ bw,
                                float* __restrict__ out) {
    int i4 = blockIdx.x * blockDim.x + threadIdx.x;
    if (i4 >= (MM * EE) / 4) return;
    int b = i4 / (SE / 4), se4 = i4 - b * (SE / 4);
    float mu = stats[b * 2 + 0], rs = stats[b * 2 + 1];
    float4 v  = ((const float4*)in)[i4];
    float4 wv = ((const float4*)w)[se4];
    float4 bv = ((const float4*)bw)[se4];
    float4 o;
    o.x = (v.x - mu) * rs * wv.x + bv.x;
    o.y = (v.y - mu) * rs * wv.y + bv.y;
    o.z = (v.z - mu) * rs * wv.z + bv.z;
    o.w = (v.w - mu) * rs * wv.w + bv.w;
    ((float4*)out)[i4] = o;
}

__global__ void ln_apply_split_kernel(const float* __restrict__ in, const float* __restrict__ stats,
                                      const float* __restrict__ w, const float* __restrict__ bw,
                                      __nv_bfloat16* __restrict__ out) {
    int i4 = blockIdx.x * blockDim.x + threadIdx.x;
    if (i4 >= (MM * EE) / 4) return;
    int b = i4 / (SE / 4), se4 = i4 - b * (SE / 4);
    int m = i4 / (EE / 4), k4 = (i4 % (EE / 4)) * 4;
    float mu = stats[b * 2 + 0], rs = stats[b * 2 + 1];
    float4 v  = ((const float4*)in)[i4];
    float4 wv = ((const float4*)w)[se4];
    float4 bv = ((const float4*)bw)[se4];
    float y[4];
    y[0] = (v.x - mu) * rs * wv.x + bv.x;
    y[1] = (v.y - mu) * rs * wv.y + bv.y;
    y[2] = (v.z - mu) * rs * wv.z + bv.z;
    y[3] = (v.w - mu) * rs * wv.w + bv.w;
    __nv_bfloat16 h[4], l[4];
    split1(y[0], h[0], l[0]); split1(y[1], h[1], l[1]);
    split1(y[2], h[2], l[2]); split1(y[3], h[3], l[3]);
    __nv_bfloat16* o = out + (long)m * KP;
    *(uint2*)(o + k4)          = *(uint2*)h;
    *(uint2*)(o + EE + k4)     = *(uint2*)l;
    *(uint2*)(o + 2 * EE + k4) = *(uint2*)h;
}

// softmax over 196 cols; emits split-bf16 P [Ph | Pl | Ph] + zero pad.
__global__ void softmax_p_kernel(const float* __restrict__ sc, __nv_bfloat16* __restrict__ P) {
    int warp = threadIdx.x >> 5, lane = threadIdx.x & 31;
    long row = (long)blockIdx.x * 4 + warp;
    if (row >= (long)ZZ * SS) return;
    const float* p = sc + row * SS;
    float v[7];
    float mx = -1e30f;
#pragma unroll
    for (int i = 0; i < 7; i++) {
        int idx = lane + i * 32;
        v[i] = (idx < SS) ? p[idx] : -1e30f;
        mx = fmaxf(mx, v[i]);
    }
#pragma unroll
    for (int o = 16; o > 0; o >>= 1) mx = fmaxf(mx, __shfl_xor_sync(0xFFFFFFFFu, mx, o));
    float sum = 0.f;
#pragma unroll
    for (int i = 0; i < 7; i++) { v[i] = expf(v[i] - mx); sum += v[i]; }
#pragma unroll
    for (int o = 16; o > 0; o >>= 1) sum += __shfl_xor_sync(0xFFFFFFFFu, sum, o);
    float inv = 1.0f / sum;
    __nv_bfloat16* o = P + row * KPV;
#pragma unroll
    for (int i = 0; i < 7; i++) {
        int idx = lane + i * 32;
        if (idx < SS) {
            float y = v[i] * inv;
            __nv_bfloat16 h, l;
            split1(y, h, l);
            o[idx] = h; o[SS + idx] = l; o[2 * SS + idx] = h;
        }
    }
    if (lane < 20) o[3 * SS + lane] = __float2bfloat16(0.f);
}

// zero pad columns (588..607) of Vt rows
__global__ void vt_pad_kernel(__nv_bfloat16* __restrict__ Vt) {
    int idx = blockIdx.x * blockDim.x + threadIdx.x;
    if (idx >= ZZ * HDIM * 10) return;
    int r = idx / 10, c = idx % 10;
    *(uint32_t*)(Vt + (long)r * KPV + 588 + c * 2) = 0u;
}

// ---------------------------------------------------------------------------
extern "C" void kernel_launch(void* const* d_in, const int* in_sizes, int n_in,
                              void* d_out, int out_size) {
    const float* x      = (const float*)d_in[0];
    const float* conv_w = (const float*)d_in[1];
    const float* conv_b = (const float*)d_in[2];
    const float* wq = (const float*)d_in[3];
    const float* bq = (const float*)d_in[4];
    const float* wk = (const float*)d_in[5];
    const float* bk = (const float*)d_in[6];
    const float* wv = (const float*)d_in[7];
    const float* bv = (const float*)d_in[8];
    const float* wo = (const float*)d_in[9];
    const float* bo = (const float*)d_in[10];
    const float* ln1w = (const float*)d_in[11];
    const float* ln1b = (const float*)d_in[12];
    const float* ln2w = (const float*)d_in[13];
    const float* ln2b = (const float*)d_in[14];
    float* out = (float*)d_out;

    float *emb, *res, *scores, *st1, *st2, *bqkv;
    float2* part;
    __nv_bfloat16 *a16, *w16, *qs, *ks, *vt, *pp;
    cudaGetSymbolAddress((void**)&emb,    g_emb);
    cudaGetSymbolAddress((void**)&res,    g_res);
    cudaGetSymbolAddress((void**)&scores, g_scores);
    cudaGetSymbolAddress((void**)&part,   g_part);
    cudaGetSymbolAddress((void**)&st1,    g_stats1);
    cudaGetSymbolAddress((void**)&st2,    g_stats2);
    cudaGetSymbolAddress((void**)&bqkv,   g_bqkv);
    cudaGetSymbolAddress((void**)&a16,    g_a16);
    cudaGetSymbolAddress((void**)&w16,    g_w16);
    cudaGetSymbolAddress((void**)&qs,     g_qs);
    cudaGetSymbolAddress((void**)&ks,     g_ks);
    cudaGetSymbolAddress((void**)&vt,     g_vt);
    cudaGetSymbolAddress((void**)&pp,     g_p);

    const int total = MM * EE;
    const size_t wstride = (size_t)EE * KP;
    const float scale = 1.0f / sqrtf((float)HDIM);

    // bias concat for QKV
    cudaMemcpyAsync(bqkv,          bq, EE * sizeof(float), cudaMemcpyDeviceToDevice);
    cudaMemcpyAsync(bqkv + EE,     bk, EE * sizeof(float), cudaMemcpyDeviceToDevice);
    cudaMemcpyAsync(bqkv + 2 * EE, bv, EE * sizeof(float), cudaMemcpyDeviceToDevice);

    // 0. split all 5 weights in one launch
    const int wtot = 5 * EE * EE / 4;
    split_wt5_kernel<<<(wtot + 255) / 256, 256>>>(conv_w, wq, wk, wv, wo, w16);

    // 1. im2col + split
    im2col_split_kernel<<<(total / 2 + 255) / 256, 256>>>(x, a16);

    // 2. patch embed -> emb (fp32)
    hmma_main_kernel<0><<<dim3(MM / 128, 6), 256>>>(a16, w16, conv_b, nullptr, emb,
                                                    nullptr, nullptr, nullptr);

    // 3. LN1: parallel partial reduce + finalize + split apply
    ln_reduce_part_kernel<<<BB * LNSEG, 256>>>(emb, part);
    ln_finalize_kernel<<<1, 64>>>(part, st1);
    ln_apply_split_kernel<<<(total / 4 + 255) / 256, 256>>>(emb, st1, ln1w, ln1b, a16);

    // 4. QKV in ONE launch -> split per-head layouts
    hmma_main_kernel<4><<<dim3(MM / 128, 18), 256>>>(a16, w16 + 1 * wstride, bqkv, nullptr,
                                                     nullptr, qs, ks, vt);
    vt_pad_kernel<<<(ZZ * HDIM * 10 + 255) / 256, 256>>>(vt);

    // 5. scores = scale * Qs . Ks^T
    hmma_bat_kernel<0><<<dim3(2, 2, ZZ), 256>>>(qs, ks, scores, nullptr,
        SS, SS, KQK, (long)SS * KQK, (long)SS * KQK,
        1, (long)SS * SS, 0, SS, scale);

    // 6. softmax -> split P
    softmax_p_kernel<<<(ZZ * SS + 3) / 4, 128>>>(scores, pp);

    // 7. attn @ V -> split-act a16
    hmma_bat_kernel<1><<<dim3(2, 2, ZZ), 256>>>(pp, vt, nullptr, a16,
        SS, HDIM, KPV, (long)SS * KPV, (long)HDIM * KPV,
        HH, 0, 0, 0, 1.0f);

    // 8. Wo + residual -> res
    hmma_main_kernel<0><<<dim3(MM / 128, 6), 256>>>(a16, w16 + 4 * wstride, bo, emb, res,
                                                    nullptr, nullptr, nullptr);

    // 9. LN2: parallel partial reduce + finalize + apply -> out
    ln_reduce_part_kernel<<<BB * LNSEG, 256>>>(res, part);
    ln_finalize_kernel<<<1, 64>>>(part, st2);
    ln_apply_kernel<<<(total / 4 + 255) / 256, 256>>>(res, st2, ln2w, ln2b, out);
}

// round 14
// speedup vs baseline: 4.5166x; 1.0255x over previous
#include <cuda_runtime.h>
#include <cuda_bf16.h>
#include <cstdint>
#include <math.h>

// ---------------------------------------------------------------------------
// ViT block, R14 (= R12 candidate; R12/R13 were broker timeouts, never ran).
// R11 + LN partial sums fused into patch-embed / Wo GEMM epilogues
// (fixed-slot deterministic tile partials), tiny tile-finalize kernel;
// standalone LN reduce passes removed.
// ---------------------------------------------------------------------------

#define BB   64
#define SS   196
#define EE   768
#define HH   4
#define HDIM 192
#define PP   16
#define GG   14
#define MM   (BB * SS)        // 12544
#define SE   (SS * EE)        // 150528
#define KP   (3 * EE)         // 2304
#define NKC  (KP / 32)        // 72
#define KQK  (3 * HDIM)       // 576
#define KPV  608              // 588 padded
#define ZZ   (BB * HH)        // 256
#define MT   (MM / 128)       // 98 m-tiles
#define NT6  (EE / 128)       // 6 n-tiles

// ---------------- scratch ---------------------------------------------------
__device__ float g_emb[MM * EE];
__device__ float g_res[MM * EE];
__device__ float g_scores[(size_t)ZZ * SS * SS];
__device__ float2 g_part[MT * NT6 * 2];
__device__ float g_stats1[BB * 2];
__device__ float g_stats2[BB * 2];
__device__ float g_bqkv[3 * EE];
__device__ __nv_bfloat16 g_a16[(size_t)MM * KP];
__device__ __nv_bfloat16 g_w16[5][(size_t)EE * KP];
__device__ __nv_bfloat16 g_qs[(size_t)ZZ * SS * KQK];
__device__ __nv_bfloat16 g_ks[(size_t)ZZ * SS * KQK];
__device__ __nv_bfloat16 g_vt[(size_t)ZZ * HDIM * KPV];
__device__ __nv_bfloat16 g_p [(size_t)ZZ * SS * KPV];

// ---------------- helpers ---------------------------------------------------
__device__ __forceinline__ uint32_t smem_u32(const void* p) {
    uint32_t a;
    asm("{ .reg .u64 t; cvta.to.shared.u64 t, %1; cvt.u32.u64 %0, t; }" : "=r"(a) : "l"(p));
    return a;
}
__device__ __forceinline__ void cp16(uint32_t saddr, const void* g) {
    asm volatile("cp.async.cg.shared.global [%0], [%1], 16;"
                 :: "r"(saddr), "l"(__cvta_generic_to_global(g)));
}
#define CP_COMMIT() asm volatile("cp.async.commit_group;" ::: "memory")
#define CP_WAIT1()  asm volatile("cp.async.wait_group 1;" ::: "memory")
#define CP_WAIT0()  asm volatile("cp.async.wait_group 0;" ::: "memory")

__device__ __forceinline__ void ldm_x4(uint32_t* r, uint32_t addr) {
    asm volatile("ldmatrix.sync.aligned.m8n8.x4.shared.b16 {%0,%1,%2,%3}, [%4];"
                 : "=r"(r[0]), "=r"(r[1]), "=r"(r[2]), "=r"(r[3]) : "r"(addr));
}
__device__ __forceinline__ void mma16816(float* c, const uint32_t* a, uint32_t b0, uint32_t b1) {
    asm volatile("mma.sync.aligned.m16n8k16.row.col.f32.bf16.bf16.f32 "
                 "{%0,%1,%2,%3}, {%4,%5,%6,%7}, {%8,%9}, {%0,%1,%2,%3};"
                 : "+f"(c[0]), "+f"(c[1]), "+f"(c[2]), "+f"(c[3])
                 : "r"(a[0]), "r"(a[1]), "r"(a[2]), "r"(a[3]), "r"(b0), "r"(b1));
}
__device__ __forceinline__ uint32_t pack2(float x, float y) {
    __nv_bfloat162 t = __floats2bfloat162_rn(x, y);
    return *(uint32_t*)&t;
}
__device__ __forceinline__ float lopart(float x) {
    return x - __bfloat162float(__float2bfloat16(x));
}

// inner compute (expects sA, sB, acc, lane constants)
#define MMA_TILE_COMPUTE()                                                     \
    _Pragma("unroll")                                                          \
    for (int ks = 0; ks < 2; ks++) {                                           \
        const int k2 = ks * 2;                                                 \
        uint32_t a[4][4], b[2][4];                                             \
        _Pragma("unroll")                                                      \
        for (int mt = 0; mt < 4; mt++) {                                       \
            int row = wm * 64 + mt * 16 + rA;                                  \
            ldm_x4(a[mt], sA + row * 64 + (((k2 + chA) ^ selA) << 4));         \
        }                                                                      \
        _Pragma("unroll")                                                      \
        for (int p = 0; p < 2; p++) {                                          \
            int row = wn * 32 + p * 16 + rB;                                   \
            ldm_x4(b[p], sB + row * 64 + (((k2 + chB) ^ selB) << 4));          \
        }                                                                      \
        _Pragma("unroll")                                                      \
        for (int mt = 0; mt < 4; mt++)                                         \
            _Pragma("unroll")                                                  \
            for (int nt = 0; nt < 4; nt++)                                     \
                mma16816(acc[mt][nt], a[mt],                                   \
                         b[nt >> 1][(nt & 1) * 2], b[nt >> 1][(nt & 1) * 2 + 1]); \
    }

#define LANE_CONSTS()                                                          \
    const int g = lane >> 3, r8 = lane & 7;                                    \
    const int rA = (g & 1) * 8 + r8, selA = (rA >> 1) & 3, chA = g >> 1;       \
    const int rB = (g >> 1) * 8 + r8, selB = (rB >> 1) & 3, chB = g & 1;

// ---------------------------------------------------------------------------
// Main HMMA GEMM: A[MM,KP] x B[N,KP]^T, tile 128x128x32, 3-stage pipeline.
// EPI 1: fp32 C (+bias, opt resid) + LN tile-partial sums (fixed slots).
// EPI 4: QKV routed split epilogue.
// ---------------------------------------------------------------------------
template <int EPI>
__global__ void __launch_bounds__(256, 2)
hmma_main_kernel(const __nv_bfloat16* __restrict__ A, const __nv_bfloat16* __restrict__ Bw,
                 const float* __restrict__ bias, const float* __restrict__ resid,
                 float* __restrict__ C, float2* __restrict__ Pp,
                 __nv_bfloat16* __restrict__ Oq, __nv_bfloat16* __restrict__ Ok,
                 __nv_bfloat16* __restrict__ Ov)
{
    __shared__ __align__(1024) char smem[49152];   // 3 stages x (A 8KB + B 8KB)
    const uint32_t sb = smem_u32(smem);
    const int tid = threadIdx.x;
    const int lane = tid & 31, wid = tid >> 5;
    const int wm = wid & 1, wn = wid >> 1;
    const int m0 = blockIdx.x * 128, n0 = blockIdx.y * 128;

    const __nv_bfloat16* Abase = A + (long)m0 * KP;
    const __nv_bfloat16* Bbase = Bw + (long)n0 * KP;

#define LOAD_STAGE(s, kc) do {                                                \
        int _ko = (kc) * 32;                                                  \
        uint32_t _base = sb + (s) * 16384;                                    \
        _Pragma("unroll")                                                     \
        for (int _i = 0; _i < 2; _i++) {                                      \
            int _lin = tid + _i * 256;                                        \
            int _row = _lin >> 2, _ch = _lin & 3;                             \
            uint32_t _sw = (uint32_t)(_row * 64 + ((_ch ^ ((_row >> 1) & 3)) << 4)); \
            cp16(_base + _sw,        Abase + (long)_row * KP + _ko + _ch * 8); \
            cp16(_base + 8192 + _sw, Bbase + (long)_row * KP + _ko + _ch * 8); \
        }                                                                     \
    } while (0)

    float acc[4][4][4] = {};
    LANE_CONSTS();

    LOAD_STAGE(0, 0); CP_COMMIT();
    LOAD_STAGE(1, 1); CP_COMMIT();

    int s = 0;
    for (int kc = 0; kc < NKC; kc++) {
        if (kc < NKC - 1) CP_WAIT1(); else CP_WAIT0();
        __syncthreads();
        if (kc + 2 < NKC) {
            int sn = s + 2; if (sn >= 3) sn -= 3;
            LOAD_STAGE(sn, kc + 2); CP_COMMIT();
        }
        const uint32_t sA = sb + s * 16384;
        const uint32_t sB = sA + 8192;
        MMA_TILE_COMPUTE();
        if (++s == 3) s = 0;
    }
#undef LOAD_STAGE

    const int which = n0 / EE;               // CTA-uniform (EPI 4)
    const int bnd = (m0 / SS + 1) * SS;      // image boundary row (EPI 1)
    float sl = 0.f, s2l = 0.f, sh = 0.f, s2h = 0.f;

#pragma unroll
    for (int mt = 0; mt < 4; mt++) {
#pragma unroll
        for (int half = 0; half < 2; half++) {
            const int gm = m0 + wm * 64 + mt * 16 + (lane >> 2) + half * 8;
#pragma unroll
            for (int nt = 0; nt < 4; nt++) {
                const int gn = n0 + wn * 32 + nt * 8 + (lane & 3) * 2;
                const float c0 = acc[mt][nt][half * 2 + 0];
                const float c1 = acc[mt][nt][half * 2 + 1];
                if (EPI == 1) {
                    float v0 = c0 + bias[gn], v1 = c1 + bias[gn + 1];
                    if (resid) {
                        float2 r = *(const float2*)(resid + (long)gm * EE + gn);
                        v0 += r.x; v1 += r.y;
                    }
                    *(float2*)(C + (long)gm * EE + gn) = make_float2(v0, v1);
                    if (gm < bnd) { sl += v0 + v1; s2l += v0 * v0 + v1 * v1; }
                    else          { sh += v0 + v1; s2h += v0 * v0 + v1 * v1; }
                } else {
                    const float y0 = c0 + bias[gn], y1 = c1 + bias[gn + 1];
                    const int gnl = gn - which * EE;
                    const int b = gm / SS, sq = gm - b * SS;
                    const int h = gnl / HDIM, d = gnl - h * HDIM;
                    if (which == 0) {        // Q: [hi | lo | hi]
                        __nv_bfloat16* o = Oq + ((long)(b * HH + h) * SS + sq) * KQK + d;
                        *(uint32_t*)(o)            = pack2(y0, y1);
                        *(uint32_t*)(o + HDIM)     = pack2(lopart(y0), lopart(y1));
                        *(uint32_t*)(o + 2 * HDIM) = pack2(y0, y1);
                    } else if (which == 1) { // K: [hi | hi | lo]
                        __nv_bfloat16* o = Ok + ((long)(b * HH + h) * SS + sq) * KQK + d;
                        *(uint32_t*)(o)            = pack2(y0, y1);
                        *(uint32_t*)(o + HDIM)     = pack2(y0, y1);
                        *(uint32_t*)(o + 2 * HDIM) = pack2(lopart(y0), lopart(y1));
                    } else {                 // Vt transposed: [Vh | Vh | Vl]
                        __nv_bfloat16* o = Ov + ((long)(b * HH + h) * HDIM + d) * KPV + sq;
                        __nv_bfloat16 h0 = __float2bfloat16(y0), h1 = __float2bfloat16(y1);
                        __nv_bfloat16 l0 = __float2bfloat16(lopart(y0)), l1 = __float2bfloat16(lopart(y1));
                        o[0] = h0;  o[SS] = h0;  o[2 * SS] = l0;
                        o += KPV;
                        o[0] = h1;  o[SS] = h1;  o[2 * SS] = l1;
                    }
                }
            }
        }
    }

    if (EPI == 1) {
        // block-reduce tile partials (smem reused; compute done)
        __syncthreads();
        float4* red = (float4*)smem;
        red[tid] = make_float4(sl, s2l, sh, s2h);
        __syncthreads();
        for (int st = 128; st > 0; st >>= 1) {
            if (tid < st) {
                float4 a = red[tid], b = red[tid + st];
                red[tid] = make_float4(a.x + b.x, a.y + b.y, a.z + b.z, a.w + b.w);
            }
            __syncthreads();
        }
        if (tid == 0) {
            float4 t = red[0];
            int base = (blockIdx.x * NT6 + blockIdx.y) * 2;
            Pp[base + 0] = make_float2(t.x, t.y);
            Pp[base + 1] = make_float2(t.z, t.w);
        }
    }
}

// ---------------------------------------------------------------------------
// Batched HMMA GEMM (NT), 3-stage single-barrier pipeline.
// EPI 0: fp32 C (z-strided). EPI 1: split-act into a16 [hi|lo|hi].
// ---------------------------------------------------------------------------
template <int EPI>
__global__ void __launch_bounds__(256, 2)
hmma_bat_kernel(const __nv_bfloat16* __restrict__ Ag, const __nv_bfloat16* __restrict__ Bg,
                float* __restrict__ C, __nv_bfloat16* __restrict__ O16,
                int Md, int Nd, int Kd, long sA_, long sB_,
                int Hdiv, long sC1, long sC2, int ldc, float scale)
{
    __shared__ __align__(1024) char smem[49152];
    const uint32_t sb = smem_u32(smem);
    const int tid = threadIdx.x;
    const int lane = tid & 31, wid = tid >> 5;
    const int wm = wid & 1, wn = wid >> 1;
    const int m0 = blockIdx.x * 128, n0 = blockIdx.y * 128;
    const int z = blockIdx.z;
    const int z1 = z / Hdiv, z2 = z - z1 * Hdiv;

    const __nv_bfloat16* Abase = Ag + (long)z * sA_;
    const __nv_bfloat16* Bbase = Bg + (long)z * sB_;
    const int nkc = Kd >> 5;

#define LOAD_STAGE_B(s, kc) do {                                              \
        int _ko = (kc) * 32;                                                  \
        uint32_t _base = sb + (s) * 16384;                                    \
        _Pragma("unroll")                                                     \
        for (int _i = 0; _i < 2; _i++) {                                      \
            int _lin = tid + _i * 256;                                        \
            int _row = _lin >> 2, _ch = _lin & 3;                             \
            uint32_t _sw = (uint32_t)(_row * 64 + ((_ch ^ ((_row >> 1) & 3)) << 4)); \
            int _ra = min(m0 + _row, Md - 1);                                 \
            int _rb = min(n0 + _row, Nd - 1);                                 \
            cp16(_base + _sw,        Abase + (long)_ra * Kd + _ko + _ch * 8); \
            cp16(_base + 8192 + _sw, Bbase + (long)_rb * Kd + _ko + _ch * 8); \
        }                                                                     \
    } while (0)

    float acc[4][4][4] = {};
    LANE_CONSTS();

    LOAD_STAGE_B(0, 0); CP_COMMIT();
    LOAD_STAGE_B(1, 1); CP_COMMIT();

    int s = 0;
    for (int kc = 0; kc < nkc; kc++) {
        if (kc < nkc - 1) CP_WAIT1(); else CP_WAIT0();
        __syncthreads();
        if (kc + 2 < nkc) {
            int sn = s + 2; if (sn >= 3) sn -= 3;
            LOAD_STAGE_B(sn, kc + 2); CP_COMMIT();
        }
        const uint32_t sA = sb + s * 16384;
        const uint32_t sB = sA + 8192;
        MMA_TILE_COMPUTE();
        if (++s == 3) s = 0;
    }
#undef LOAD_STAGE_B

    float* Cz = (EPI == 0) ? (C + (long)z1 * sC1 + (long)z2 * sC2) : nullptr;
#pragma unroll
    for (int mt = 0; mt < 4; mt++) {
#pragma unroll
        for (int half = 0; half < 2; half++) {
            const int gm = m0 + wm * 64 + mt * 16 + (lane >> 2) + half * 8;
            if (gm >= Md) continue;
#pragma unroll
            for (int nt = 0; nt < 4; nt++) {
                const int gn = n0 + wn * 32 + nt * 8 + (lane & 3) * 2;
                if (gn >= Nd) continue;
                const float c0 = acc[mt][nt][half * 2 + 0] * scale;
                const float c1 = acc[mt][nt][half * 2 + 1] * scale;
                if (EPI == 0) {
                    *(float2*)(Cz + (long)gm * ldc + gn) = make_float2(c0, c1);
                } else {
                    const long row = (long)z1 * SS + gm;
                    const int  col = z2 * HDIM + gn;
                    __nv_bfloat16* o = O16 + row * KP + col;
                    *(uint32_t*)(o)          = pack2(c0, c1);
                    *(uint32_t*)(o + EE)     = pack2(lopart(c0), lopart(c1));
                    *(uint32_t*)(o + 2 * EE) = pack2(c0, c1);
                }
            }
        }
    }
}

// ---------------------------------------------------------------------------
// splits / im2col / LN / softmax
// ---------------------------------------------------------------------------
__device__ __forceinline__ void split1(float x, __nv_bfloat16& h, __nv_bfloat16& l) {
    h = __float2bfloat16(x);
    l = __float2bfloat16(x - __bfloat162float(h));
}

__global__ void split_wt5_kernel(const float* __restrict__ w0, const float* __restrict__ w1,
                                 const float* __restrict__ w2, const float* __restrict__ w3,
                                 const float* __restrict__ w4, __nv_bfloat16* __restrict__ out) {
    const int per = EE * EE / 4;
    int idx = blockIdx.x * blockDim.x + threadIdx.x;
    if (idx >= 5 * per) return;
    int wsel = idx / per, r = idx - wsel * per;
    const float* w = (wsel == 0) ? w0 : (wsel == 1) ? w1 : (wsel == 2) ? w2 : (wsel == 3) ? w3 : w4;
    int n = r / (EE / 4), k4 = (r % (EE / 4)) * 4;
    float4 v = ((const float4*)w)[r];
    __nv_bfloat16 h[4], l[4];
    split1(v.x, h[0], l[0]); split1(v.y, h[1], l[1]);
    split1(v.z, h[2], l[2]); split1(v.w, h[3], l[3]);
    __nv_bfloat16* o = out + (size_t)wsel * EE * KP + (long)n * KP;
    *(uint2*)(o + k4)          = *(uint2*)h;
    *(uint2*)(o + EE + k4)     = *(uint2*)h;
    *(uint2*)(o + 2 * EE + k4) = *(uint2*)l;
}

__global__ void im2col_split_kernel(const float* __restrict__ x, __nv_bfloat16* __restrict__ out) {
    int idx = blockIdx.x * blockDim.x + threadIdx.x;
    if (idx >= MM * EE / 2) return;
    int e2 = idx % (EE / 2);
    int s  = (idx / (EE / 2)) % SS;
    int b  = idx / ((EE / 2) * SS);
    int e  = e2 * 2;
    int c = e >> 8, r = e & 255, py = r >> 4, px = r & 15;
    int gy = s / GG, gx = s % GG;
    const float* xp = x + (((long)(b * 3 + c) * 224) + gy * PP + py) * 224 + gx * PP + px;
    float2 v = *(const float2*)xp;
    __nv_bfloat16 h[2], l[2];
    split1(v.x, h[0], l[0]); split1(v.y, h[1], l[1]);
    __nv_bfloat16* o = out + (long)(b * SS + s) * KP;
    *(uint32_t*)(o + e)          = *(uint32_t*)h;
    *(uint32_t*)(o + EE + e)     = *(uint32_t*)l;
    *(uint32_t*)(o + 2 * EE + e) = *(uint32_t*)h;
}

// fold GEMM tile partials -> per-image stats. Deterministic fixed-slot walk.
__global__ void ln_finalize_tiles_kernel(const float2* __restrict__ part, float* __restrict__ stats) {
    int b = threadIdx.x;
    if (b >= BB) return;
    float s = 0.f, s2 = 0.f;
    int t0 = (b * SS) >> 7, t1 = (b * SS + SS - 1) >> 7;
    for (int t = t0; t <= t1; t++) {
        int il = (t * 128) / SS;
        int slot = (il == b) ? 0 : 1;
#pragma unroll
        for (int n = 0; n < NT6; n++) {
            float2 v = part[((t * NT6 + n) * 2) + slot];
            s += v.x; s2 += v.y;
        }
    }
    float mu  = s / (float)SE;
    float var = s2 / (float)SE - mu * mu;
    stats[b * 2 + 0] = mu;
    stats[b * 2 + 1] = rsqrtf(var + 1e-5f);
}

__global__ void ln_apply_kernel(const float* __restrict__ in, const float* __restrict__ stats,
                                const float* __restrict__ w, const float* __restrict__ bw,
                                float* __restrict__ out) {
    int i4 = blockIdx.x * blockDim.x + threadIdx.x;
    if (i4 >= (MM * EE) / 4) return;
    int b = i4 / (SE / 4), se4 = i4 - b * (SE / 4);
    float mu = stats[b * 2 + 0], rs = stats[b * 2 + 1];
    float4 v  = ((const float4*)in)[i4];
    float4 wv = ((const float4*)w)[se4];
    float4 bv = ((const float4*)bw)[se4];
    float4 o;
    o.x = (v.x - mu) * rs * wv.x + bv.x;
    o.y = (v.y - mu) * rs * wv.y + bv.y;
    o.z = (v.z - mu) * rs * wv.z + bv.z;
    o.w = (v.w - mu) * rs * wv.w + bv.w;
    ((float4*)out)[i4] = o;
}

__global__ void ln_apply_split_kernel(const float* __restrict__ in, const float* __restrict__ stats,
                                      const float* __restrict__ w, const float* __restrict__ bw,
                                      __nv_bfloat16* __restrict__ out) {
    int i4 = blockIdx.x * blockDim.x + threadIdx.x;
    if (i4 >= (MM * EE) / 4) return;
    int b = i4 / (SE / 4), se4 = i4 - b * (SE / 4);
    int m = i4 / (EE / 4), k4 = (i4 % (EE / 4)) * 4;
    float mu = stats[b * 2 + 0], rs = stats[b * 2 + 1];
    float4 v  = ((const float4*)in)[i4];
    float4 wv = ((const float4*)w)[se4];
    float4 bv = ((const float4*)bw)[se4];
    float y[4];
    y[0] = (v.x - mu) * rs * wv.x + bv.x;
    y[1] = (v.y - mu) * rs * wv.y + bv.y;
    y[2] = (v.z - mu) * rs * wv.z + bv.z;
    y[3] = (v.w - mu) * rs * wv.w + bv.w;
    __nv_bfloat16 h[4], l[4];
    split1(y[0], h[0], l[0]); split1(y[1], h[1], l[1]);
    split1(y[2], h[2], l[2]); split1(y[3], h[3], l[3]);
    __nv_bfloat16* o = out + (long)m * KP;
    *(uint2*)(o + k4)          = *(uint2*)h;
    *(uint2*)(o + EE + k4)     = *(uint2*)l;
    *(uint2*)(o + 2 * EE + k4) = *(uint2*)h;
}

// softmax over 196 cols; emits split-bf16 P [Ph | Pl | Ph] + zero pad.
__global__ void softmax_p_kernel(const float* __restrict__ sc, __nv_bfloat16* __restrict__ P) {
    int warp = threadIdx.x >> 5, lane = threadIdx.x & 31;
    long row = (long)blockIdx.x * 4 + warp;
    if (row >= (long)ZZ * SS) return;
    const float* p = sc + row * SS;
    float v[7];
    float mx = -1e30f;
#pragma unroll
    for (int i = 0; i < 7; i++) {
        int idx = lane + i * 32;
        v[i] = (idx < SS) ? p[idx] : -1e30f;
        mx = fmaxf(mx, v[i]);
    }
#pragma unroll
    for (int o = 16; o > 0; o >>= 1) mx = fmaxf(mx, __shfl_xor_sync(0xFFFFFFFFu, mx, o));
    float sum = 0.f;
#pragma unroll
    for (int i = 0; i < 7; i++) { v[i] = expf(v[i] - mx); sum += v[i]; }
#pragma unroll
    for (int o = 16; o > 0; o >>= 1) sum += __shfl_xor_sync(0xFFFFFFFFu, sum, o);
    float inv = 1.0f / sum;
    __nv_bfloat16* o = P + row * KPV;
#pragma unroll
    for (int i = 0; i < 7; i++) {
        int idx = lane + i * 32;
        if (idx < SS) {
            float y = v[i] * inv;
            __nv_bfloat16 h, l;
            split1(y, h, l);
            o[idx] = h; o[SS + idx] = l; o[2 * SS + idx] = h;
        }
    }
    if (lane < 20) o[3 * SS + lane] = __float2bfloat16(0.f);
}

// zero pad columns (588..607) of Vt rows
__global__ void vt_pad_kernel(__nv_bfloat16* __restrict__ Vt) {
    int idx = blockIdx.x * blockDim.x + threadIdx.x;
    if (idx >= ZZ * HDIM * 10) return;
    int r = idx / 10, c = idx % 10;
    *(uint32_t*)(Vt + (long)r * KPV + 588 + c * 2) = 0u;
}

// ---------------------------------------------------------------------------
extern "C" void kernel_launch(void* const* d_in, const int* in_sizes, int n_in,
                              void* d_out, int out_size) {
    const float* x      = (const float*)d_in[0];
    const float* conv_w = (const float*)d_in[1];
    const float* conv_b = (const float*)d_in[2];
    const float* wq = (const float*)d_in[3];
    const float* bq = (const float*)d_in[4];
    const float* wk = (const float*)d_in[5];
    const float* bk = (const float*)d_in[6];
    const float* wv = (const float*)d_in[7];
    const float* bv = (const float*)d_in[8];
    const float* wo = (const float*)d_in[9];
    const float* bo = (const float*)d_in[10];
    const float* ln1w = (const float*)d_in[11];
    const float* ln1b = (const float*)d_in[12];
    const float* ln2w = (const float*)d_in[13];
    const float* ln2b = (const float*)d_in[14];
    float* out = (float*)d_out;

    float *emb, *res, *scores, *st1, *st2, *bqkv;
    float2* part;
    __nv_bfloat16 *a16, *w16, *qs, *ks, *vt, *pp;
    cudaGetSymbolAddress((void**)&emb,    g_emb);
    cudaGetSymbolAddress((void**)&res,    g_res);
    cudaGetSymbolAddress((void**)&scores, g_scores);
    cudaGetSymbolAddress((void**)&part,   g_part);
    cudaGetSymbolAddress((void**)&st1,    g_stats1);
    cudaGetSymbolAddress((void**)&st2,    g_stats2);
    cudaGetSymbolAddress((void**)&bqkv,   g_bqkv);
    cudaGetSymbolAddress((void**)&a16,    g_a16);
    cudaGetSymbolAddress((void**)&w16,    g_w16);
    cudaGetSymbolAddress((void**)&qs,     g_qs);
    cudaGetSymbolAddress((void**)&ks,     g_ks);
    cudaGetSymbolAddress((void**)&vt,     g_vt);
    cudaGetSymbolAddress((void**)&pp,     g_p);

    const int total = MM * EE;
    const size_t wstride = (size_t)EE * KP;
    const float scale = 1.0f / sqrtf((float)HDIM);

    // bias concat for QKV
    cudaMemcpyAsync(bqkv,          bq, EE * sizeof(float), cudaMemcpyDeviceToDevice);
    cudaMemcpyAsync(bqkv + EE,     bk, EE * sizeof(float), cudaMemcpyDeviceToDevice);
    cudaMemcpyAsync(bqkv + 2 * EE, bv, EE * sizeof(float), cudaMemcpyDeviceToDevice);

    // 0. split all 5 weights in one launch
    const int wtot = 5 * EE * EE / 4;
    split_wt5_kernel<<<(wtot + 255) / 256, 256>>>(conv_w, wq, wk, wv, wo, w16);

    // 1. im2col + split
    im2col_split_kernel<<<(total / 2 + 255) / 256, 256>>>(x, a16);

    // 2. patch embed -> emb (fp32) + LN1 tile partials
    hmma_main_kernel<1><<<dim3(MT, NT6), 256>>>(a16, w16, conv_b, nullptr, emb, part,
                                                nullptr, nullptr, nullptr);

    // 3. LN1: finalize tiles + split apply
    ln_finalize_tiles_kernel<<<1, 64>>>(part, st1);
    ln_apply_split_kernel<<<(total / 4 + 255) / 256, 256>>>(emb, st1, ln1w, ln1b, a16);

    // 4. QKV in ONE launch -> split per-head layouts
    hmma_main_kernel<4><<<dim3(MT, 18), 256>>>(a16, w16 + 1 * wstride, bqkv, nullptr,
                                               nullptr, nullptr, qs, ks, vt);
    vt_pad_kernel<<<(ZZ * HDIM * 10 + 255) / 256, 256>>>(vt);

    // 5. scores = scale * Qs . Ks^T
    hmma_bat_kernel<0><<<dim3(2, 2, ZZ), 256>>>(qs, ks, scores, nullptr,
        SS, SS, KQK, (long)SS * KQK, (long)SS * KQK,
        1, (long)SS * SS, 0, SS, scale);

    // 6. softmax -> split P
    softmax_p_kernel<<<(ZZ * SS + 3) / 4, 128>>>(scores, pp);

    // 7. attn @ V -> split-act a16
    hmma_bat_kernel<1><<<dim3(2, 2, ZZ), 256>>>(pp, vt, nullptr, a16,
        SS, HDIM, KPV, (long)SS * KPV, (long)HDIM * KPV,
        HH, 0, 0, 0, 1.0f);

    // 8. Wo + residual -> res (fp32) + LN2 tile partials
    hmma_main_kernel<1><<<dim3(MT, NT6), 256>>>(a16, w16 + 4 * wstride, bo, emb, res, part,
                                                nullptr, nullptr, nullptr);

    // 9. LN2: finalize tiles + apply -> out
    ln_finalize_tiles_kernel<<<1, 64>>>(part, st2);
    ln_apply_kernel<<<(total / 4 + 255) / 256, 256>>>(res, st2, ln2w, ln2b, out);
}